// round 1
// baseline (speedup 1.0000x reference)
#include <cuda_runtime.h>
#include <math.h>

// Problem constants
#define BB   16
#define SSQ  384
#define DDQ  512
#define HHQ  8
#define HDQ  64
#define LLQ  4
#define KKQ  7
#define MMQ  (BB*SSQ)      // 6144 rows
#define BHQ  (BB*HHQ)      // 128 batch*heads

// ---------------- scratch (device globals; no allocation allowed) -----------
__device__ float g_res[MMQ*DDQ];
__device__ float g_cur[MMQ*DDQ];
__device__ float g_tmp[MMQ*DDQ];
__device__ float g_q  [MMQ*DDQ];
__device__ float g_k  [MMQ*DDQ];
__device__ float g_v  [MMQ*DDQ];
__device__ float g_probs[(size_t)BHQ*SSQ*SSQ];   // 75.5 MB

// ---------------- helpers ----------------------------------------------------
__inline__ __device__ float blockReduceSum128(float val) {
    __shared__ float sh[4];
    int lane = threadIdx.x & 31, w = threadIdx.x >> 5;
    #pragma unroll
    for (int o = 16; o; o >>= 1) val += __shfl_xor_sync(0xffffffffu, val, o);
    if (lane == 0) sh[w] = val;
    __syncthreads();
    float r = sh[0] + sh[1] + sh[2] + sh[3];
    __syncthreads();
    return r;
}

// ---------------- pos-encoding add: res = x + PE -----------------------------
__global__ void k_addpos(const float* __restrict__ x) {
    int idx = blockIdx.x * 256 + threadIdx.x;
    if (idx >= MMQ * DDQ) return;
    int c = idx & (DDQ - 1);
    int s = (idx >> 9) % SSQ;
    double div = pow(10000.0, (double)(2 * c) / (double)DDQ);
    double ang = (double)s / div;
    float pe = (c & 1) ? (float)cos(ang) : (float)sin(ang);
    g_res[idx] = x[idx] + pe;
}

// ---------------- layernorm: out = LN(in) * g + b ----------------------------
// one block (128 threads) per row of 512
__global__ void k_ln(const float* __restrict__ in, float* __restrict__ out,
                     const float* __restrict__ gm, const float* __restrict__ bt) {
    int row = blockIdx.x;
    int t = threadIdx.x;
    float4 v = ((const float4*)(in + row * DDQ))[t];
    float s = v.x + v.y + v.z + v.w;
    float mean = blockReduceSum128(s) * (1.0f / DDQ);
    float dx = v.x - mean, dy = v.y - mean, dz = v.z - mean, dw = v.w - mean;
    float s2 = dx*dx + dy*dy + dz*dz + dw*dw;
    float var = blockReduceSum128(s2) * (1.0f / DDQ);
    float inv = rsqrtf(var + 1e-5f);
    int c = t * 4;
    float4 o;
    o.x = dx * inv * gm[c+0] + bt[c+0];
    o.y = dy * inv * gm[c+1] + bt[c+1];
    o.z = dz * inv * gm[c+2] + bt[c+2];
    o.w = dw * inv * gm[c+3] + bt[c+3];
    ((float4*)(out + row * DDQ))[t] = o;
}

// ---------------- depthwise conv (K=7, same padding) --------------------------
__global__ void k_dwconv(const float* __restrict__ in, float* __restrict__ out,
                         const float* __restrict__ dw) {
    int idx = blockIdx.x * 256 + threadIdx.x;
    if (idx >= MMQ * DDQ) return;
    int c = idx & (DDQ - 1);
    int bs = idx >> 9;
    int s = bs % SSQ, b = bs / SSQ;
    const float* wr = dw + c * KKQ;
    float acc = 0.f;
    #pragma unroll
    for (int k = 0; k < KKQ; k++) {
        int ss = s + k - 3;
        if (ss >= 0 && ss < SSQ)
            acc += in[((b * SSQ + ss) << 9) + c] * wr[k];
    }
    out[idx] = acc;
}

// ---------------- main GEMM: Y[M,512] = X[M,512] @ W[512,512]^T + epilogue ----
// 64x64 tile, 256 threads, 4x4 per thread, TK=16, smem transposed for LDS.128
template<int RELU, int ADDRES, int SCATTER>
__global__ void k_gemm(const float* __restrict__ X, const float* __restrict__ W,
                       const float* __restrict__ bias, const float* __restrict__ res,
                       float* __restrict__ out) {
    __shared__ float As[16][68];
    __shared__ float Bs[16][68];
    const int m0 = blockIdx.y * 64, n0 = blockIdx.x * 64;
    const int tid = threadIdx.x;
    const int lrow = tid >> 2, lk = (tid & 3) * 4;
    const int ty = tid >> 4, tx = tid & 15;
    float acc[4][4] = {};
    const float* xp = X + (m0 + lrow) * DDQ + lk;
    const float* wp = W + (n0 + lrow) * DDQ + lk;
    for (int kt = 0; kt < DDQ; kt += 16) {
        float4 av = *(const float4*)(xp + kt);
        float4 bv = *(const float4*)(wp + kt);
        __syncthreads();
        As[lk+0][lrow] = av.x; As[lk+1][lrow] = av.y;
        As[lk+2][lrow] = av.z; As[lk+3][lrow] = av.w;
        Bs[lk+0][lrow] = bv.x; Bs[lk+1][lrow] = bv.y;
        Bs[lk+2][lrow] = bv.z; Bs[lk+3][lrow] = bv.w;
        __syncthreads();
        #pragma unroll
        for (int kk = 0; kk < 16; kk++) {
            float4 a = *(const float4*)&As[kk][ty * 4];
            float4 b = *(const float4*)&Bs[kk][tx * 4];
            acc[0][0] += a.x*b.x; acc[0][1] += a.x*b.y; acc[0][2] += a.x*b.z; acc[0][3] += a.x*b.w;
            acc[1][0] += a.y*b.x; acc[1][1] += a.y*b.y; acc[1][2] += a.y*b.z; acc[1][3] += a.y*b.w;
            acc[2][0] += a.z*b.x; acc[2][1] += a.z*b.y; acc[2][2] += a.z*b.z; acc[2][3] += a.z*b.w;
            acc[3][0] += a.w*b.x; acc[3][1] += a.w*b.y; acc[3][2] += a.w*b.z; acc[3][3] += a.w*b.w;
        }
    }
    #pragma unroll
    for (int i = 0; i < 4; i++) {
        int m = m0 + ty * 4 + i;
        #pragma unroll
        for (int j = 0; j < 4; j++) {
            int n = n0 + tx * 4 + j;
            float v = acc[i][j] + bias[n];
            if (RELU)   v = fmaxf(v, 0.f);
            if (ADDRES) v += res[m * DDQ + n];
            if (SCATTER) {
                int b = m / SSQ, s = m % SSQ;
                int h = n >> 6, hd = n & 63;
                out[(((b * HHQ + h) * SSQ + s) << 6) + hd] = v;
            } else {
                out[m * DDQ + n] = v;
            }
        }
    }
}

// ---------------- attention scores: E = mask(QK^T / 8) ------------------------
// per (bh): M=384, N=384, K=64.  grid (6, 6, 128)
__global__ void k_scores(const int* __restrict__ mask) {
    __shared__ float As[16][68];
    __shared__ float Bs[16][68];
    const int bh = blockIdx.z, b = bh >> 3;
    const float* Q  = g_q + (size_t)bh * SSQ * HDQ;
    const float* Km = g_k + (size_t)bh * SSQ * HDQ;
    float* E = g_probs + (size_t)bh * SSQ * SSQ;
    const int m0 = blockIdx.y * 64, n0 = blockIdx.x * 64;
    const int tid = threadIdx.x;
    const int lrow = tid >> 2, lk = (tid & 3) * 4;
    const int ty = tid >> 4, tx = tid & 15;
    float acc[4][4] = {};
    const float* xp = Q  + (m0 + lrow) * HDQ + lk;
    const float* wp = Km + (n0 + lrow) * HDQ + lk;
    for (int kt = 0; kt < HDQ; kt += 16) {
        float4 av = *(const float4*)(xp + kt);
        float4 bv = *(const float4*)(wp + kt);
        __syncthreads();
        As[lk+0][lrow] = av.x; As[lk+1][lrow] = av.y;
        As[lk+2][lrow] = av.z; As[lk+3][lrow] = av.w;
        Bs[lk+0][lrow] = bv.x; Bs[lk+1][lrow] = bv.y;
        Bs[lk+2][lrow] = bv.z; Bs[lk+3][lrow] = bv.w;
        __syncthreads();
        #pragma unroll
        for (int kk = 0; kk < 16; kk++) {
            float4 a = *(const float4*)&As[kk][ty * 4];
            float4 b2 = *(const float4*)&Bs[kk][tx * 4];
            acc[0][0] += a.x*b2.x; acc[0][1] += a.x*b2.y; acc[0][2] += a.x*b2.z; acc[0][3] += a.x*b2.w;
            acc[1][0] += a.y*b2.x; acc[1][1] += a.y*b2.y; acc[1][2] += a.y*b2.z; acc[1][3] += a.y*b2.w;
            acc[2][0] += a.z*b2.x; acc[2][1] += a.z*b2.y; acc[2][2] += a.z*b2.z; acc[2][3] += a.z*b2.w;
            acc[3][0] += a.w*b2.x; acc[3][1] += a.w*b2.y; acc[3][2] += a.w*b2.z; acc[3][3] += a.w*b2.w;
        }
    }
    #pragma unroll
    for (int i = 0; i < 4; i++) {
        int m = m0 + ty * 4 + i;
        #pragma unroll
        for (int j = 0; j < 4; j++) {
            int n = n0 + tx * 4 + j;
            float v = acc[i][j] * 0.125f;
            if (mask[b * SSQ + n] == 1) v = -1e10f;
            E[m * SSQ + n] = v;
        }
    }
}

// ---------------- row softmax over 384 ---------------------------------------
__global__ void k_softmax() {
    float* p = g_probs + (size_t)blockIdx.x * SSQ;
    int t = threadIdx.x;
    __shared__ float sh[4];
    float v0 = p[t], v1 = p[t + 128], v2 = p[t + 256];
    float mx = fmaxf(fmaxf(v0, v1), v2);
    #pragma unroll
    for (int o = 16; o; o >>= 1) mx = fmaxf(mx, __shfl_xor_sync(0xffffffffu, mx, o));
    if ((t & 31) == 0) sh[t >> 5] = mx;
    __syncthreads();
    mx = fmaxf(fmaxf(sh[0], sh[1]), fmaxf(sh[2], sh[3]));
    __syncthreads();
    float e0 = expf(v0 - mx), e1 = expf(v1 - mx), e2 = expf(v2 - mx);
    float s = e0 + e1 + e2;
    #pragma unroll
    for (int o = 16; o; o >>= 1) s += __shfl_xor_sync(0xffffffffu, s, o);
    if ((t & 31) == 0) sh[t >> 5] = s;
    __syncthreads();
    s = sh[0] + sh[1] + sh[2] + sh[3];
    float inv = 1.f / s;
    p[t] = e0 * inv; p[t + 128] = e1 * inv; p[t + 256] = e2 * inv;
}

// ---------------- PV: A = P @ V, written back to [B,S,D] layout ---------------
// per (bh): M=384, N=64, K=384.  grid (6, 128)
__global__ void k_av() {
    __shared__ float As[16][68];
    __shared__ float Bs[16][68];
    const int bh = blockIdx.y;
    const int b = bh >> 3, h = bh & 7;
    const float* P = g_probs + (size_t)bh * SSQ * SSQ;
    const float* V = g_v + (size_t)bh * SSQ * HDQ;
    const int m0 = blockIdx.x * 64;
    const int tid = threadIdx.x;
    const int lrow = tid >> 2, lk = (tid & 3) * 4;      // A loader (64 x 16)
    const int vrow = tid >> 4, vc = (tid & 15) * 4;     // B loader (16 x 64)
    const int ty = tid >> 4, tx = tid & 15;
    float acc[4][4] = {};
    for (int kt = 0; kt < SSQ; kt += 16) {
        float4 av = *(const float4*)&P[(m0 + lrow) * SSQ + kt + lk];
        float4 bv = *(const float4*)&V[(kt + vrow) * HDQ + vc];
        __syncthreads();
        As[lk+0][lrow] = av.x; As[lk+1][lrow] = av.y;
        As[lk+2][lrow] = av.z; As[lk+3][lrow] = av.w;
        *(float4*)&Bs[vrow][vc] = bv;
        __syncthreads();
        #pragma unroll
        for (int kk = 0; kk < 16; kk++) {
            float4 a = *(const float4*)&As[kk][ty * 4];
            float4 b2 = *(const float4*)&Bs[kk][tx * 4];
            acc[0][0] += a.x*b2.x; acc[0][1] += a.x*b2.y; acc[0][2] += a.x*b2.z; acc[0][3] += a.x*b2.w;
            acc[1][0] += a.y*b2.x; acc[1][1] += a.y*b2.y; acc[1][2] += a.y*b2.z; acc[1][3] += a.y*b2.w;
            acc[2][0] += a.z*b2.x; acc[2][1] += a.z*b2.y; acc[2][2] += a.z*b2.z; acc[2][3] += a.z*b2.w;
            acc[3][0] += a.w*b2.x; acc[3][1] += a.w*b2.y; acc[3][2] += a.w*b2.z; acc[3][3] += a.w*b2.w;
        }
    }
    #pragma unroll
    for (int i = 0; i < 4; i++) {
        int m = m0 + ty * 4 + i;
        #pragma unroll
        for (int j = 0; j < 4; j++) {
            int n = tx * 4 + j;
            g_tmp[(b * SSQ + m) * DDQ + h * HDQ + n] = acc[i][j];
        }
    }
}

// ---------------- host orchestration -----------------------------------------
extern "C" void kernel_launch(void* const* d_in, const int* in_sizes, int n_in,
                              void* d_out, int out_size) {
    const float* x    = (const float*)d_in[0];
    const int*   mask = (const int*)  d_in[1];
    const float* dw_w = (const float*)d_in[2];
    const float* pw_w = (const float*)d_in[3];
    const float* pw_b = (const float*)d_in[4];
    const float* cg   = (const float*)d_in[5];
    const float* cb   = (const float*)d_in[6];
    const float* pg   = (const float*)d_in[7];
    const float* pb   = (const float*)d_in[8];
    const float* wq   = (const float*)d_in[9];
    const float* bq   = (const float*)d_in[10];
    const float* wk   = (const float*)d_in[11];
    const float* bk   = (const float*)d_in[12];
    const float* wv   = (const float*)d_in[13];
    const float* bv   = (const float*)d_in[14];
    const float* wo   = (const float*)d_in[15];
    const float* bo   = (const float*)d_in[16];
    const float* fg   = (const float*)d_in[17];
    const float* fb   = (const float*)d_in[18];
    const float* fw   = (const float*)d_in[19];
    const float* fbi  = (const float*)d_in[20];
    float* out = (float*)d_out;

    float *p_res, *p_cur, *p_tmp, *p_q, *p_k, *p_v;
    cudaGetSymbolAddress((void**)&p_res, g_res);
    cudaGetSymbolAddress((void**)&p_cur, g_cur);
    cudaGetSymbolAddress((void**)&p_tmp, g_tmp);
    cudaGetSymbolAddress((void**)&p_q,   g_q);
    cudaGetSymbolAddress((void**)&p_k,   g_k);
    cudaGetSymbolAddress((void**)&p_v,   g_v);

    const int NELEM = MMQ * DDQ;
    dim3 gemm_grid(8, 96);   // N/64, M/64

    // 1. res = x + PE ; cur = LN(res)
    k_addpos<<<(NELEM + 255) / 256, 256>>>(x);
    k_ln<<<MMQ, 128>>>(p_res, p_cur, pg, pb);

    // 2. conv stack
    for (int l = 0; l < LLQ; l++) {
        k_dwconv<<<(NELEM + 255) / 256, 256>>>(p_cur, p_tmp, dw_w + l * DDQ * KKQ);
        // res = relu(tmp @ pw^T + pwb) + res
        k_gemm<1, 1, 0><<<gemm_grid, 256>>>(p_tmp, pw_w + l * DDQ * DDQ,
                                            pw_b + l * DDQ, p_res, p_res);
        k_ln<<<MMQ, 128>>>(p_res, p_cur, cg + l * DDQ, cb + l * DDQ);
    }

    // 3. attention
    k_gemm<0, 0, 1><<<gemm_grid, 256>>>(p_cur, wq, bq, p_res, p_q);
    k_gemm<0, 0, 1><<<gemm_grid, 256>>>(p_cur, wk, bk, p_res, p_k);
    k_gemm<0, 0, 1><<<gemm_grid, 256>>>(p_cur, wv, bv, p_res, p_v);
    k_scores<<<dim3(6, 6, BHQ), 256>>>(mask);
    k_softmax<<<BHQ * SSQ, 128>>>();
    k_av<<<dim3(6, BHQ), 256>>>();
    // res = tmp @ wo^T + bo + res
    k_gemm<0, 1, 0><<<gemm_grid, 256>>>(p_tmp, wo, bo, p_res, p_res);

    // 4. feedforward: out = relu(LN(res) @ fw^T + fb) + res
    k_ln<<<MMQ, 128>>>(p_res, p_cur, fg, fb);
    k_gemm<1, 1, 0><<<gemm_grid, 256>>>(p_cur, fw, fbi, p_res, out);
}

// round 4
// speedup vs baseline: 5.0523x; 5.0523x over previous
#include <cuda_runtime.h>
#include <cuda_fp16.h>
#include <math.h>
#include <stdint.h>

// Problem constants
#define BB   16
#define SSQ  384
#define DDQ  512
#define HHQ  8
#define HDQ  64
#define LLQ  4
#define KKQ  7
#define MMQ  (BB*SSQ)      // 6144 rows
#define BHQ  (BB*HHQ)      // 128 batch*heads

// ---------------- scratch (device globals; no allocation allowed) -----------
__device__ float g_res[MMQ*DDQ];
__device__ float g_cur[MMQ*DDQ];
__device__ float g_probs[(size_t)BHQ*SSQ*SSQ];          // fp32 energies  75.5MB
__device__ __half g_xh[MMQ*DDQ];                        // fp16 GEMM A operand
__device__ __half g_wh[9*DDQ*DDQ];                      // fp16 weights
__device__ __half g_qh[MMQ*DDQ];
__device__ __half g_kh[MMQ*DDQ];
__device__ __half g_vh[MMQ*DDQ];
__device__ __half g_ph[(size_t)BHQ*SSQ*SSQ];            // fp16 probs    37.7MB

// ================= low-level helpers =========================================
__device__ __forceinline__ uint32_t smem_u32(const void* p) {
    uint32_t a;
    asm("{ .reg .u64 t; cvta.to.shared.u64 t, %1; cvt.u32.u64 %0, t; }" : "=r"(a) : "l"(p));
    return a;
}
__device__ __forceinline__ void cpa16(uint32_t dst, const void* src) {
    asm volatile("cp.async.cg.shared.global [%0], [%1], 16;" :: "r"(dst), "l"(src) : "memory");
}
#define CP_COMMIT() asm volatile("cp.async.commit_group;" ::: "memory")
#define CP_WAIT(n)  asm volatile("cp.async.wait_group %0;" :: "n"(n) : "memory")

__device__ __forceinline__ void ldsm4(uint32_t* r, uint32_t addr) {
    asm volatile("ldmatrix.sync.aligned.m8n8.x4.shared.b16 {%0,%1,%2,%3}, [%4];"
                 : "=r"(r[0]), "=r"(r[1]), "=r"(r[2]), "=r"(r[3]) : "r"(addr));
}
__device__ __forceinline__ void ldsm4t(uint32_t* r, uint32_t addr) {
    asm volatile("ldmatrix.sync.aligned.m8n8.x4.trans.shared.b16 {%0,%1,%2,%3}, [%4];"
                 : "=r"(r[0]), "=r"(r[1]), "=r"(r[2]), "=r"(r[3]) : "r"(addr));
}
__device__ __forceinline__ void hmma(float* d, const uint32_t* a, uint32_t b0, uint32_t b1) {
    asm volatile(
        "mma.sync.aligned.m16n8k16.row.col.f32.f16.f16.f32 "
        "{%0,%1,%2,%3}, {%4,%5,%6,%7}, {%8,%9}, {%0,%1,%2,%3};"
        : "+f"(d[0]), "+f"(d[1]), "+f"(d[2]), "+f"(d[3])
        : "r"(a[0]), "r"(a[1]), "r"(a[2]), "r"(a[3]), "r"(b0), "r"(b1));
}

// ================= dense GEMM: Y[6144,512] = X@W^T + epilogue ================
// X fp16 [M,512], W fp16 [N,512] (row-major N,K == B col-major). BM=128 BN=64
// BK=32, 256 threads (8 warps, 4m x 2n, warp tile 32x32), cp.async 2-stage.
template<int RELU, int ADDRES, int SCATTER>
__global__ void __launch_bounds__(256)
k_gemm_h(const __half* __restrict__ X, const __half* __restrict__ W,
         const float* __restrict__ bias, const float* __restrict__ res,
         float* __restrict__ outf, __half* __restrict__ outh) {
    __shared__ __half As[2][128 * 32];
    __shared__ __half Bs[2][64 * 32];
    const int tid = threadIdx.x, lane = tid & 31, wid = tid >> 5;
    const int wm = wid >> 1, wn = wid & 1;
    const int m0 = blockIdx.y * 128, n0 = blockIdx.x * 64;
    float acc[2][4][4] = {};

    const uint32_t aBase[2] = { smem_u32(&As[0][0]), smem_u32(&As[1][0]) };
    const uint32_t bBase[2] = { smem_u32(&Bs[0][0]), smem_u32(&Bs[1][0]) };

    // initial load kt=0 buf=0
    {
        #pragma unroll
        for (int i = 0; i < 2; i++) {
            int q = tid + i * 256; int r = q >> 2, c = q & 3;
            cpa16(aBase[0] + r * 64 + ((c ^ (r & 3)) * 16),
                  X + (size_t)(m0 + r) * DDQ + c * 8);
        }
        { int r = tid >> 2, c = tid & 3;
          cpa16(bBase[0] + r * 64 + ((c ^ (r & 3)) * 16),
                W + (size_t)(n0 + r) * DDQ + c * 8); }
        CP_COMMIT();
    }

    #pragma unroll 1
    for (int kt = 0; kt < 16; kt++) {
        int buf = kt & 1;
        if (kt < 15) {
            int nb = buf ^ 1;
            #pragma unroll
            for (int i = 0; i < 2; i++) {
                int q = tid + i * 256; int r = q >> 2, c = q & 3;
                cpa16(aBase[nb] + r * 64 + ((c ^ (r & 3)) * 16),
                      X + (size_t)(m0 + r) * DDQ + (kt + 1) * 32 + c * 8);
            }
            { int r = tid >> 2, c = tid & 3;
              cpa16(bBase[nb] + r * 64 + ((c ^ (r & 3)) * 16),
                    W + (size_t)(n0 + r) * DDQ + (kt + 1) * 32 + c * 8); }
            CP_COMMIT();
            CP_WAIT(1);
        } else {
            CP_WAIT(0);
        }
        __syncthreads();
        #pragma unroll
        for (int ks = 0; ks < 2; ks++) {
            uint32_t a[2][4], b[2][4];
            #pragma unroll
            for (int mt = 0; mt < 2; mt++) {
                int r = wm * 32 + mt * 16 + (lane & 15);
                int c = ks * 2 + (lane >> 4);
                ldsm4(a[mt], aBase[buf] + r * 64 + ((c ^ (r & 3)) * 16));
            }
            #pragma unroll
            for (int np = 0; np < 2; np++) {
                int nr = wn * 32 + np * 16 + (lane & 7) + ((lane >> 4) << 3);
                int c = ks * 2 + ((lane >> 3) & 1);
                ldsm4(b[np], bBase[buf] + nr * 64 + ((c ^ (nr & 3)) * 16));
            }
            #pragma unroll
            for (int mt = 0; mt < 2; mt++)
                #pragma unroll
                for (int nt = 0; nt < 4; nt++)
                    hmma(acc[mt][nt], a[mt], b[nt >> 1][(nt & 1) * 2], b[nt >> 1][(nt & 1) * 2 + 1]);
        }
        __syncthreads();
    }

    // epilogue
    #pragma unroll
    for (int mt = 0; mt < 2; mt++) {
        int r = m0 + wm * 32 + mt * 16 + (lane >> 2);
        #pragma unroll
        for (int nt = 0; nt < 4; nt++) {
            int cl = wn * 32 + nt * 8 + (lane & 3) * 2;
            int n = n0 + cl;
            float b0 = bias[n], b1 = bias[n + 1];
            float v00 = acc[mt][nt][0] + b0, v01 = acc[mt][nt][1] + b1;
            float v10 = acc[mt][nt][2] + b0, v11 = acc[mt][nt][3] + b1;
            if (RELU) {
                v00 = fmaxf(v00, 0.f); v01 = fmaxf(v01, 0.f);
                v10 = fmaxf(v10, 0.f); v11 = fmaxf(v11, 0.f);
            }
            if (ADDRES) {
                float2 r0 = *(const float2*)&res[(size_t)r * DDQ + n];
                float2 r1 = *(const float2*)&res[(size_t)(r + 8) * DDQ + n];
                v00 += r0.x; v01 += r0.y; v10 += r1.x; v11 += r1.y;
            }
            if (SCATTER) {
                int h = n >> 6, hd = n & 63;
                int b_ = r / SSQ, s = r % SSQ;
                *(__half2*)&outh[(((size_t)(b_ * HHQ + h) * SSQ + s) << 6) + hd] =
                    __floats2half2_rn(v00, v01);
                int b2 = (r + 8) / SSQ, s2 = (r + 8) % SSQ;
                *(__half2*)&outh[(((size_t)(b2 * HHQ + h) * SSQ + s2) << 6) + hd] =
                    __floats2half2_rn(v10, v11);
            } else {
                *(float2*)&outf[(size_t)r * DDQ + n] = make_float2(v00, v01);
                *(float2*)&outf[(size_t)(r + 8) * DDQ + n] = make_float2(v10, v11);
            }
        }
    }
}

// ================= scores: E = mask(Q K^T / 8), fp32 out =====================
// per bh: M=384,N=384,K=64. BM=BN=128, single-stage smem, 8 warps (4m x 2n).
__global__ void __launch_bounds__(256)
k_scores_h(const int* __restrict__ mask) {
    __shared__ __half Qs[128 * 64];
    __shared__ __half Ks[128 * 64];
    const int bh = blockIdx.z, b = bh >> 3;
    const __half* Q = g_qh + (size_t)bh * SSQ * HDQ;
    const __half* K = g_kh + (size_t)bh * SSQ * HDQ;
    float* E = g_probs + (size_t)bh * SSQ * SSQ;
    const int m0 = blockIdx.y * 128, n0 = blockIdx.x * 128;
    const int tid = threadIdx.x, lane = tid & 31, wid = tid >> 5;
    const int wm = wid >> 1, wn = wid & 1;
    const uint32_t qB = smem_u32(Qs), kB = smem_u32(Ks);

    #pragma unroll
    for (int i = 0; i < 4; i++) {
        int q = tid + i * 256;     // 1024 chunks each
        int r = q >> 3, c = q & 7;
        cpa16(qB + r * 128 + ((c ^ (r & 7)) * 16), Q + (size_t)(m0 + r) * HDQ + c * 8);
        cpa16(kB + r * 128 + ((c ^ (r & 7)) * 16), K + (size_t)(n0 + r) * HDQ + c * 8);
    }
    CP_COMMIT(); CP_WAIT(0);
    __syncthreads();

    float acc[2][8][4] = {};
    #pragma unroll
    for (int ks = 0; ks < 4; ks++) {
        uint32_t a[2][4], bfr[4][4];
        #pragma unroll
        for (int mt = 0; mt < 2; mt++) {
            int r = wm * 32 + mt * 16 + (lane & 15);
            int c = ks * 2 + (lane >> 4);
            ldsm4(a[mt], qB + r * 128 + ((c ^ (r & 7)) * 16));
        }
        #pragma unroll
        for (int np = 0; np < 4; np++) {
            int nr = wn * 64 + np * 16 + (lane & 7) + ((lane >> 4) << 3);
            int c = ks * 2 + ((lane >> 3) & 1);
            ldsm4(bfr[np], kB + nr * 128 + ((c ^ (nr & 7)) * 16));
        }
        #pragma unroll
        for (int mt = 0; mt < 2; mt++)
            #pragma unroll
            for (int nt = 0; nt < 8; nt++)
                hmma(acc[mt][nt], a[mt], bfr[nt >> 1][(nt & 1) * 2], bfr[nt >> 1][(nt & 1) * 2 + 1]);
    }

    #pragma unroll
    for (int mt = 0; mt < 2; mt++) {
        int r = m0 + wm * 32 + mt * 16 + (lane >> 2);
        #pragma unroll
        for (int nt = 0; nt < 8; nt++) {
            int c = n0 + wn * 64 + nt * 8 + (lane & 3) * 2;
            float ma = (mask[b * SSQ + c]     == 1) ? -1e10f : 0.f;
            float mb = (mask[b * SSQ + c + 1] == 1) ? -1e10f : 0.f;
            *(float2*)&E[(size_t)r * SSQ + c] =
                make_float2(acc[mt][nt][0] * 0.125f + ma, acc[mt][nt][1] * 0.125f + mb);
            *(float2*)&E[(size_t)(r + 8) * SSQ + c] =
                make_float2(acc[mt][nt][2] * 0.125f + ma, acc[mt][nt][3] * 0.125f + mb);
        }
    }
}

// ================= softmax rows of 384: fp32 in -> fp16 out ==================
__global__ void k_softmax() {
    const float* p = g_probs + (size_t)blockIdx.x * SSQ;
    __half* o = g_ph + (size_t)blockIdx.x * SSQ;
    int t = threadIdx.x;
    __shared__ float sh[4];
    float v0 = p[t], v1 = p[t + 128], v2 = p[t + 256];
    float mx = fmaxf(fmaxf(v0, v1), v2);
    #pragma unroll
    for (int of = 16; of; of >>= 1) mx = fmaxf(mx, __shfl_xor_sync(0xffffffffu, mx, of));
    if ((t & 31) == 0) sh[t >> 5] = mx;
    __syncthreads();
    mx = fmaxf(fmaxf(sh[0], sh[1]), fmaxf(sh[2], sh[3]));
    __syncthreads();
    float e0 = expf(v0 - mx), e1 = expf(v1 - mx), e2 = expf(v2 - mx);
    float s = e0 + e1 + e2;
    #pragma unroll
    for (int of = 16; of; of >>= 1) s += __shfl_xor_sync(0xffffffffu, s, of);
    if ((t & 31) == 0) sh[t >> 5] = s;
    __syncthreads();
    s = sh[0] + sh[1] + sh[2] + sh[3];
    float inv = 1.f / s;
    o[t] = __float2half(e0 * inv);
    o[t + 128] = __float2half(e1 * inv);
    o[t + 256] = __float2half(e2 * inv);
}

// ================= PV: A = P(fp16) @ V(fp16) -> g_xh [B,S,D] =================
// per bh: M=384,N=64,K=384. BM=128 BN=64 BK=32, 2-stage. warps 4m x 2n (32x32).
__global__ void __launch_bounds__(256)
k_av_h() {
    __shared__ __half Ps[2][128 * 32];
    __shared__ __half Vs[2][32 * 64];
    const int bh = blockIdx.y, b = bh >> 3, h = bh & 7;
    const __half* P = g_ph + (size_t)bh * SSQ * SSQ;
    const __half* V = g_vh + (size_t)bh * SSQ * HDQ;
    const int m0 = blockIdx.x * 128;
    const int tid = threadIdx.x, lane = tid & 31, wid = tid >> 5;
    const int wm = wid >> 1, wn = wid & 1;
    const uint32_t pB[2] = { smem_u32(&Ps[0][0]), smem_u32(&Ps[1][0]) };
    const uint32_t vB[2] = { smem_u32(&Vs[0][0]), smem_u32(&Vs[1][0]) };
    float acc[2][4][4] = {};

    // initial load
    #pragma unroll
    for (int i = 0; i < 2; i++) {
        int q = tid + i * 256; int r = q >> 2, c = q & 3;
        cpa16(pB[0] + r * 64 + ((c ^ (r & 3)) * 16), P + (size_t)(m0 + r) * SSQ + c * 8);
    }
    { int r = tid >> 3, c = tid & 7;
      cpa16(vB[0] + r * 128 + ((c ^ (r & 7)) * 16), V + (size_t)r * HDQ + c * 8); }
    CP_COMMIT();

    #pragma unroll 1
    for (int kt = 0; kt < 12; kt++) {
        int buf = kt & 1;
        if (kt < 11) {
            int nb = buf ^ 1;
            #pragma unroll
            for (int i = 0; i < 2; i++) {
                int q = tid + i * 256; int r = q >> 2, c = q & 3;
                cpa16(pB[nb] + r * 64 + ((c ^ (r & 3)) * 16),
                      P + (size_t)(m0 + r) * SSQ + (kt + 1) * 32 + c * 8);
            }
            { int r = tid >> 3, c = tid & 7;
              cpa16(vB[nb] + r * 128 + ((c ^ (r & 7)) * 16),
                    V + (size_t)((kt + 1) * 32 + r) * HDQ + c * 8); }
            CP_COMMIT();
            CP_WAIT(1);
        } else {
            CP_WAIT(0);
        }
        __syncthreads();
        #pragma unroll
        for (int ks = 0; ks < 2; ks++) {
            uint32_t a[2][4], bfr[2][4];
            #pragma unroll
            for (int mt = 0; mt < 2; mt++) {
                int r = wm * 32 + mt * 16 + (lane & 15);
                int c = ks * 2 + (lane >> 4);
                ldsm4(a[mt], pB[buf] + r * 64 + ((c ^ (r & 3)) * 16));
            }
            #pragma unroll
            for (int np = 0; np < 2; np++) {
                int row = ks * 16 + (lane & 7) + ((lane >> 3) & 1) * 8;
                int c = wn * 4 + np * 2 + (lane >> 4);
                ldsm4t(bfr[np], vB[buf] + row * 128 + ((c ^ (row & 7)) * 16));
            }
            #pragma unroll
            for (int mt = 0; mt < 2; mt++)
                #pragma unroll
                for (int nt = 0; nt < 4; nt++)
                    hmma(acc[mt][nt], a[mt], bfr[nt >> 1][(nt & 1) * 2], bfr[nt >> 1][(nt & 1) * 2 + 1]);
        }
        __syncthreads();
    }

    #pragma unroll
    for (int mt = 0; mt < 2; mt++) {
        int s = m0 + wm * 32 + mt * 16 + (lane >> 2);
        #pragma unroll
        for (int nt = 0; nt < 4; nt++) {
            int hd = wn * 32 + nt * 8 + (lane & 3) * 2;
            *(__half2*)&g_xh[((size_t)(b * SSQ + s)) * DDQ + h * HDQ + hd] =
                __floats2half2_rn(acc[mt][nt][0], acc[mt][nt][1]);
            *(__half2*)&g_xh[((size_t)(b * SSQ + s + 8)) * DDQ + h * HDQ + hd] =
                __floats2half2_rn(acc[mt][nt][2], acc[mt][nt][3]);
        }
    }
}

// ================= elementwise / reduction kernels ===========================
__inline__ __device__ float blockReduceSum128(float val) {
    __shared__ float sh[4];
    int lane = threadIdx.x & 31, w = threadIdx.x >> 5;
    #pragma unroll
    for (int o = 16; o; o >>= 1) val += __shfl_xor_sync(0xffffffffu, val, o);
    if (lane == 0) sh[w] = val;
    __syncthreads();
    float r = sh[0] + sh[1] + sh[2] + sh[3];
    __syncthreads();
    return r;
}

__global__ void k_addpos(const float* __restrict__ x) {
    int idx = blockIdx.x * 256 + threadIdx.x;
    if (idx >= MMQ * DDQ) return;
    int c = idx & (DDQ - 1);
    int s = (idx >> 9) % SSQ;
    float inv = exp2f(-((float)(2 * c) * (1.0f / 512.0f)) * 13.2877123795494f);
    float ang = (float)s * inv;
    float pe = (c & 1) ? cosf(ang) : sinf(ang);
    g_res[idx] = x[idx] + pe;
}

// layernorm; OUTF32 -> fp32 to `out`, OUTH -> fp16 to g_xh
template<int OUTF32, int OUTH>
__global__ void k_ln(const float* __restrict__ in, float* __restrict__ out,
                     const float* __restrict__ gm, const float* __restrict__ bt) {
    int row = blockIdx.x;
    int t = threadIdx.x;
    float4 v = ((const float4*)(in + (size_t)row * DDQ))[t];
    float s = v.x + v.y + v.z + v.w;
    float mean = blockReduceSum128(s) * (1.0f / DDQ);
    float dx = v.x - mean, dy = v.y - mean, dz = v.z - mean, dw = v.w - mean;
    float s2 = dx*dx + dy*dy + dz*dz + dw*dw;
    float var = blockReduceSum128(s2) * (1.0f / DDQ);
    float inv = rsqrtf(var + 1e-5f);
    int c = t * 4;
    float4 o;
    o.x = dx * inv * gm[c+0] + bt[c+0];
    o.y = dy * inv * gm[c+1] + bt[c+1];
    o.z = dz * inv * gm[c+2] + bt[c+2];
    o.w = dw * inv * gm[c+3] + bt[c+3];
    if (OUTF32) ((float4*)(out + (size_t)row * DDQ))[t] = o;
    if (OUTH) {
        __half2* hp = (__half2*)(g_xh + (size_t)row * DDQ + c);
        hp[0] = __floats2half2_rn(o.x, o.y);
        hp[1] = __floats2half2_rn(o.z, o.w);
    }
}

// depthwise conv (K=7, same padding), fp32 in -> fp16 out (GEMM A operand)
__global__ void k_dwconv(const float* __restrict__ in,
                         const float* __restrict__ dw) {
    int idx = blockIdx.x * 256 + threadIdx.x;
    if (idx >= MMQ * DDQ) return;
    int c = idx & (DDQ - 1);
    int bs = idx >> 9;
    int s = bs % SSQ, b = bs / SSQ;
    const float* wr = dw + c * KKQ;
    float acc = 0.f;
    #pragma unroll
    for (int k = 0; k < KKQ; k++) {
        int ss = s + k - 3;
        if (ss >= 0 && ss < SSQ)
            acc += in[(((size_t)b * SSQ + ss) << 9) + c] * wr[k];
    }
    g_xh[idx] = __float2half(acc);
}

__global__ void k_f2h(const float* __restrict__ in, __half* __restrict__ out, int n) {
    int i = blockIdx.x * 256 + threadIdx.x;
    if (i < n) out[i] = __float2half(in[i]);
}

// ---------------- host orchestration -----------------------------------------
extern "C" void kernel_launch(void* const* d_in, const int* in_sizes, int n_in,
                              void* d_out, int out_size) {
    const float* x    = (const float*)d_in[0];
    const int*   mask = (const int*)  d_in[1];
    const float* dw_w = (const float*)d_in[2];
    const float* pw_w = (const float*)d_in[3];
    const float* pw_b = (const float*)d_in[4];
    const float* cg   = (const float*)d_in[5];
    const float* cb   = (const float*)d_in[6];
    const float* pg   = (const float*)d_in[7];
    const float* pb   = (const float*)d_in[8];
    const float* wq   = (const float*)d_in[9];
    const float* bq   = (const float*)d_in[10];
    const float* wk   = (const float*)d_in[11];
    const float* bk   = (const float*)d_in[12];
    const float* wv   = (const float*)d_in[13];
    const float* bv   = (const float*)d_in[14];
    const float* wo   = (const float*)d_in[15];
    const float* bo   = (const float*)d_in[16];
    const float* fg   = (const float*)d_in[17];
    const float* fb   = (const float*)d_in[18];
    const float* fw   = (const float*)d_in[19];
    const float* fbi  = (const float*)d_in[20];
    float* out = (float*)d_out;

    float *p_res, *p_cur;
    __half *p_xh, *p_wh, *p_qh, *p_kh, *p_vh;
    cudaGetSymbolAddress((void**)&p_res, g_res);
    cudaGetSymbolAddress((void**)&p_cur, g_cur);
    cudaGetSymbolAddress((void**)&p_xh,  g_xh);
    cudaGetSymbolAddress((void**)&p_wh,  g_wh);
    cudaGetSymbolAddress((void**)&p_qh,  g_qh);
    cudaGetSymbolAddress((void**)&p_kh,  g_kh);
    cudaGetSymbolAddress((void**)&p_vh,  g_vh);

    const int NELEM = MMQ * DDQ;
    const int WSZ = DDQ * DDQ;  // 262144
    dim3 dg(8, 48);             // N/64, M/128

    // 0. weights -> fp16
    k_f2h<<<(4 * WSZ + 255) / 256, 256>>>(pw_w, p_wh + 0 * (size_t)WSZ, 4 * WSZ);
    k_f2h<<<(WSZ + 255) / 256, 256>>>(wq, p_wh + 4 * (size_t)WSZ, WSZ);
    k_f2h<<<(WSZ + 255) / 256, 256>>>(wk, p_wh + 5 * (size_t)WSZ, WSZ);
    k_f2h<<<(WSZ + 255) / 256, 256>>>(wv, p_wh + 6 * (size_t)WSZ, WSZ);
    k_f2h<<<(WSZ + 255) / 256, 256>>>(wo, p_wh + 7 * (size_t)WSZ, WSZ);
    k_f2h<<<(WSZ + 255) / 256, 256>>>(fw, p_wh + 8 * (size_t)WSZ, WSZ);

    // 1. res = x + PE ; cur = LN(res)
    k_addpos<<<(NELEM + 255) / 256, 256>>>(x);
    k_ln<1, 0><<<MMQ, 128>>>(p_res, p_cur, pg, pb);

    // 2. conv stack
    for (int l = 0; l < LLQ; l++) {
        k_dwconv<<<(NELEM + 255) / 256, 256>>>(p_cur, dw_w + l * DDQ * KKQ);
        k_gemm_h<1, 1, 0><<<dg, 256>>>(p_xh, p_wh + (size_t)l * WSZ,
                                       pw_b + l * DDQ, p_res, p_res, nullptr);
        if (l < LLQ - 1)
            k_ln<1, 0><<<MMQ, 128>>>(p_res, p_cur, cg + l * DDQ, cb + l * DDQ);
        else
            k_ln<0, 1><<<MMQ, 128>>>(p_res, p_cur, cg + l * DDQ, cb + l * DDQ);
    }

    // 3. attention
    k_gemm_h<0, 0, 1><<<dg, 256>>>(p_xh, p_wh + 4 * (size_t)WSZ, bq, p_res, nullptr, p_qh);
    k_gemm_h<0, 0, 1><<<dg, 256>>>(p_xh, p_wh + 5 * (size_t)WSZ, bk, p_res, nullptr, p_kh);
    k_gemm_h<0, 0, 1><<<dg, 256>>>(p_xh, p_wh + 6 * (size_t)WSZ, bv, p_res, nullptr, p_vh);
    k_scores_h<<<dim3(3, 3, BHQ), 256>>>(mask);
    k_softmax<<<BHQ * SSQ, 128>>>();
    k_av_h<<<dim3(3, BHQ), 256>>>();
    k_gemm_h<0, 1, 0><<<dg, 256>>>(p_xh, p_wh + 7 * (size_t)WSZ, bo, p_res, p_res, nullptr);

    // 4. feedforward: out = relu(LN(res) @ fw^T + fb) + res
    k_ln<0, 1><<<MMQ, 128>>>(p_res, p_cur, fg, fb);
    k_gemm_h<1, 1, 0><<<dg, 256>>>(p_xh, p_wh + 8 * (size_t)WSZ, fbi, p_res, out, nullptr);
}

// round 5
// speedup vs baseline: 5.5713x; 1.1027x over previous
#include <cuda_runtime.h>
#include <cuda_fp16.h>
#include <math.h>
#include <stdint.h>

// Problem constants
#define BB   16
#define SSQ  384
#define DDQ  512
#define HHQ  8
#define HDQ  64
#define LLQ  4
#define KKQ  7
#define MMQ  (BB*SSQ)      // 6144 rows
#define BHQ  (BB*HHQ)      // 128 batch*heads

// ---------------- scratch (device globals; no allocation allowed) -----------
__device__ float g_res[MMQ*DDQ];                        // fp32 residual spine
__device__ __half g_xh[MMQ*DDQ];                        // fp16 GEMM A operand
__device__ __half g_wh[9*DDQ*DDQ];                      // fp16 weights
__device__ __half g_qh[MMQ*DDQ];                        // LN16 out (conv) / Q (attn)
__device__ __half g_kh[MMQ*DDQ];
__device__ __half g_vh[MMQ*DDQ];

// ================= low-level helpers =========================================
__device__ __forceinline__ uint32_t smem_u32(const void* p) {
    uint32_t a;
    asm("{ .reg .u64 t; cvta.to.shared.u64 t, %1; cvt.u32.u64 %0, t; }" : "=r"(a) : "l"(p));
    return a;
}
__device__ __forceinline__ void cpa16(uint32_t dst, const void* src) {
    asm volatile("cp.async.cg.shared.global [%0], [%1], 16;" :: "r"(dst), "l"(src) : "memory");
}
#define CP_COMMIT() asm volatile("cp.async.commit_group;" ::: "memory")
#define CP_WAIT(n)  asm volatile("cp.async.wait_group %0;" :: "n"(n) : "memory")

__device__ __forceinline__ void ldsm4(uint32_t* r, uint32_t addr) {
    asm volatile("ldmatrix.sync.aligned.m8n8.x4.shared.b16 {%0,%1,%2,%3}, [%4];"
                 : "=r"(r[0]), "=r"(r[1]), "=r"(r[2]), "=r"(r[3]) : "r"(addr));
}
__device__ __forceinline__ void ldsm4t(uint32_t* r, uint32_t addr) {
    asm volatile("ldmatrix.sync.aligned.m8n8.x4.trans.shared.b16 {%0,%1,%2,%3}, [%4];"
                 : "=r"(r[0]), "=r"(r[1]), "=r"(r[2]), "=r"(r[3]) : "r"(addr));
}
__device__ __forceinline__ void hmma(float* d, const uint32_t* a, uint32_t b0, uint32_t b1) {
    asm volatile(
        "mma.sync.aligned.m16n8k16.row.col.f32.f16.f16.f32 "
        "{%0,%1,%2,%3}, {%4,%5,%6,%7}, {%8,%9}, {%0,%1,%2,%3};"
        : "+f"(d[0]), "+f"(d[1]), "+f"(d[2]), "+f"(d[3])
        : "r"(a[0]), "r"(a[1]), "r"(a[2]), "r"(a[3]), "r"(b0), "r"(b1));
}
__device__ __forceinline__ uint32_t packh2(float x, float y) {
    __half2 h = __floats2half2_rn(x, y);
    return *reinterpret_cast<uint32_t*>(&h);
}

// ================= dense GEMM: Y[6144,512] = X@W^T + epilogue ================
// X fp16 [M,512], W fp16 [N,512]. BM=128 BN=64 BK=32, 256 threads
// (8 warps, 4m x 2n, warp tile 32x32), cp.async 2-stage.
template<int RELU, int ADDRES, int SCATTER>
__global__ void __launch_bounds__(256)
k_gemm_h(const __half* __restrict__ X, const __half* __restrict__ W,
         const float* __restrict__ bias, const float* __restrict__ res,
         float* __restrict__ outf, __half* __restrict__ outh) {
    __shared__ __half As[2][128 * 32];
    __shared__ __half Bs[2][64 * 32];
    const int tid = threadIdx.x, lane = tid & 31, wid = tid >> 5;
    const int wm = wid >> 1, wn = wid & 1;
    const int m0 = blockIdx.y * 128, n0 = blockIdx.x * 64;
    float acc[2][4][4] = {};

    const uint32_t aBase[2] = { smem_u32(&As[0][0]), smem_u32(&As[1][0]) };
    const uint32_t bBase[2] = { smem_u32(&Bs[0][0]), smem_u32(&Bs[1][0]) };

    // initial load kt=0 buf=0
    {
        #pragma unroll
        for (int i = 0; i < 2; i++) {
            int q = tid + i * 256; int r = q >> 2, c = q & 3;
            cpa16(aBase[0] + r * 64 + ((c ^ (r & 3)) * 16),
                  X + (size_t)(m0 + r) * DDQ + c * 8);
        }
        { int r = tid >> 2, c = tid & 3;
          cpa16(bBase[0] + r * 64 + ((c ^ (r & 3)) * 16),
                W + (size_t)(n0 + r) * DDQ + c * 8); }
        CP_COMMIT();
    }

    #pragma unroll 1
    for (int kt = 0; kt < 16; kt++) {
        int buf = kt & 1;
        if (kt < 15) {
            int nb = buf ^ 1;
            #pragma unroll
            for (int i = 0; i < 2; i++) {
                int q = tid + i * 256; int r = q >> 2, c = q & 3;
                cpa16(aBase[nb] + r * 64 + ((c ^ (r & 3)) * 16),
                      X + (size_t)(m0 + r) * DDQ + (kt + 1) * 32 + c * 8);
            }
            { int r = tid >> 2, c = tid & 3;
              cpa16(bBase[nb] + r * 64 + ((c ^ (r & 3)) * 16),
                    W + (size_t)(n0 + r) * DDQ + (kt + 1) * 32 + c * 8); }
            CP_COMMIT();
            CP_WAIT(1);
        } else {
            CP_WAIT(0);
        }
        __syncthreads();
        #pragma unroll
        for (int ks = 0; ks < 2; ks++) {
            uint32_t a[2][4], b[2][4];
            #pragma unroll
            for (int mt = 0; mt < 2; mt++) {
                int r = wm * 32 + mt * 16 + (lane & 15);
                int c = ks * 2 + (lane >> 4);
                ldsm4(a[mt], aBase[buf] + r * 64 + ((c ^ (r & 3)) * 16));
            }
            #pragma unroll
            for (int np = 0; np < 2; np++) {
                int nr = wn * 32 + np * 16 + (lane & 7) + ((lane >> 4) << 3);
                int c = ks * 2 + ((lane >> 3) & 1);
                ldsm4(b[np], bBase[buf] + nr * 64 + ((c ^ (nr & 3)) * 16));
            }
            #pragma unroll
            for (int mt = 0; mt < 2; mt++)
                #pragma unroll
                for (int nt = 0; nt < 4; nt++)
                    hmma(acc[mt][nt], a[mt], b[nt >> 1][(nt & 1) * 2], b[nt >> 1][(nt & 1) * 2 + 1]);
        }
        __syncthreads();
    }

    // epilogue
    #pragma unroll
    for (int mt = 0; mt < 2; mt++) {
        int r = m0 + wm * 32 + mt * 16 + (lane >> 2);
        #pragma unroll
        for (int nt = 0; nt < 4; nt++) {
            int cl = wn * 32 + nt * 8 + (lane & 3) * 2;
            int n = n0 + cl;
            float b0 = bias[n], b1 = bias[n + 1];
            float v00 = acc[mt][nt][0] + b0, v01 = acc[mt][nt][1] + b1;
            float v10 = acc[mt][nt][2] + b0, v11 = acc[mt][nt][3] + b1;
            if (RELU) {
                v00 = fmaxf(v00, 0.f); v01 = fmaxf(v01, 0.f);
                v10 = fmaxf(v10, 0.f); v11 = fmaxf(v11, 0.f);
            }
            if (ADDRES) {
                float2 r0 = *(const float2*)&res[(size_t)r * DDQ + n];
                float2 r1 = *(const float2*)&res[(size_t)(r + 8) * DDQ + n];
                v00 += r0.x; v01 += r0.y; v10 += r1.x; v11 += r1.y;
            }
            if (SCATTER) {
                int h = n >> 6, hd = n & 63;
                int b_ = r / SSQ, s = r % SSQ;
                *(__half2*)&outh[(((size_t)(b_ * HHQ + h) * SSQ + s) << 6) + hd] =
                    __floats2half2_rn(v00, v01);
                int b2 = (r + 8) / SSQ, s2 = (r + 8) % SSQ;
                *(__half2*)&outh[(((size_t)(b2 * HHQ + h) * SSQ + s2) << 6) + hd] =
                    __floats2half2_rn(v10, v11);
            } else {
                *(float2*)&outf[(size_t)r * DDQ + n] = make_float2(v00, v01);
                *(float2*)&outf[(size_t)(r + 8) * DDQ + n] = make_float2(v10, v11);
            }
        }
    }
}

// ================= flash attention ==========================================
// One block = (q-tile of 128 rows) x (one bh). 8 warps, warp = 16 q-rows x all cols.
// Loop 3 chunks of 128 keys: S = QK^T/8 + mask, online softmax, O += P V.
__global__ void __launch_bounds__(256)
k_flash(const int* __restrict__ mask) {
    __shared__ __half Qs[128 * 64];
    __shared__ __half Ks[128 * 64];
    __shared__ __half Vs[128 * 64];
    __shared__ int misk[128];
    const int bh = blockIdx.y, b = bh >> 3, h = bh & 7;
    const __half* Q = g_qh + (size_t)bh * SSQ * HDQ;
    const __half* K = g_kh + (size_t)bh * SSQ * HDQ;
    const __half* V = g_vh + (size_t)bh * SSQ * HDQ;
    const int m0 = blockIdx.x * 128;
    const int tid = threadIdx.x, lane = tid & 31, w = tid >> 5;
    const uint32_t qB = smem_u32(Qs), kB = smem_u32(Ks), vB = smem_u32(Vs);

    // Q tile load (once)
    #pragma unroll
    for (int i = 0; i < 4; i++) {
        int q = tid + i * 256; int r = q >> 3, c = q & 7;
        cpa16(qB + r * 128 + ((c ^ (r & 7)) * 16), Q + (size_t)(m0 + r) * HDQ + c * 8);
    }

    float o[8][4] = {};
    float mrow0 = -3.0e38f, mrow1 = -3.0e38f, lrow0 = 0.f, lrow1 = 0.f;
    const float LOG2E = 1.4426950408889634f;

    #pragma unroll 1
    for (int kc = 0; kc < 3; kc++) {
        // load K,V chunk + mask
        if (tid < 128) misk[tid] = mask[b * SSQ + kc * 128 + tid];
        #pragma unroll
        for (int i = 0; i < 4; i++) {
            int q = tid + i * 256; int r = q >> 3, c = q & 7;
            cpa16(kB + r * 128 + ((c ^ (r & 7)) * 16),
                  K + (size_t)(kc * 128 + r) * HDQ + c * 8);
            cpa16(vB + r * 128 + ((c ^ (r & 7)) * 16),
                  V + (size_t)(kc * 128 + r) * HDQ + c * 8);
        }
        CP_COMMIT(); CP_WAIT(0);
        __syncthreads();

        // S = Q K^T  (warp: 16 rows x 128 cols)
        float s[16][4] = {};
        #pragma unroll
        for (int ks = 0; ks < 4; ks++) {
            uint32_t a[4];
            { int r = w * 16 + (lane & 15);
              int c = ks * 2 + (lane >> 4);
              ldsm4(a, qB + r * 128 + ((c ^ (r & 7)) * 16)); }
            #pragma unroll
            for (int np = 0; np < 8; np++) {
                uint32_t bf[4];
                int nr = np * 16 + (lane & 7) + ((lane >> 4) << 3);
                int c = ks * 2 + ((lane >> 3) & 1);
                ldsm4(bf, kB + nr * 128 + ((c ^ (nr & 7)) * 16));
                hmma(s[np * 2 + 0], a, bf[0], bf[1]);
                hmma(s[np * 2 + 1], a, bf[2], bf[3]);
            }
        }

        // scale + mask; per-row max
        float mx0 = -3.0e38f, mx1 = -3.0e38f;
        #pragma unroll
        for (int nt = 0; nt < 16; nt++) {
            int nc = nt * 8 + (lane & 3) * 2;
            int f0 = misk[nc], f1 = misk[nc + 1];
            s[nt][0] = f0 ? -1e10f : s[nt][0] * 0.125f;
            s[nt][1] = f1 ? -1e10f : s[nt][1] * 0.125f;
            s[nt][2] = f0 ? -1e10f : s[nt][2] * 0.125f;
            s[nt][3] = f1 ? -1e10f : s[nt][3] * 0.125f;
            mx0 = fmaxf(mx0, fmaxf(s[nt][0], s[nt][1]));
            mx1 = fmaxf(mx1, fmaxf(s[nt][2], s[nt][3]));
        }
        #pragma unroll
        for (int of = 1; of <= 2; of <<= 1) {
            mx0 = fmaxf(mx0, __shfl_xor_sync(0xffffffffu, mx0, of));
            mx1 = fmaxf(mx1, __shfl_xor_sync(0xffffffffu, mx1, of));
        }
        float mn0 = fmaxf(mrow0, mx0), mn1 = fmaxf(mrow1, mx1);
        float al0 = exp2f((mrow0 - mn0) * LOG2E);
        float al1 = exp2f((mrow1 - mn1) * LOG2E);
        mrow0 = mn0; mrow1 = mn1;

        // p = exp(s - m); row sums
        float sum0 = 0.f, sum1 = 0.f;
        #pragma unroll
        for (int nt = 0; nt < 16; nt++) {
            s[nt][0] = exp2f((s[nt][0] - mn0) * LOG2E);
            s[nt][1] = exp2f((s[nt][1] - mn0) * LOG2E);
            s[nt][2] = exp2f((s[nt][2] - mn1) * LOG2E);
            s[nt][3] = exp2f((s[nt][3] - mn1) * LOG2E);
            sum0 += s[nt][0] + s[nt][1];
            sum1 += s[nt][2] + s[nt][3];
        }
        #pragma unroll
        for (int of = 1; of <= 2; of <<= 1) {
            sum0 += __shfl_xor_sync(0xffffffffu, sum0, of);
            sum1 += __shfl_xor_sync(0xffffffffu, sum1, of);
        }
        lrow0 = lrow0 * al0 + sum0;
        lrow1 = lrow1 * al1 + sum1;

        // rescale O
        #pragma unroll
        for (int t = 0; t < 8; t++) {
            o[t][0] *= al0; o[t][1] *= al0; o[t][2] *= al1; o[t][3] *= al1;
        }

        // O += P V  (P from s regs: C(m16n8) -> A(m16n8k16) repack)
        #pragma unroll
        for (int kg = 0; kg < 8; kg++) {
            uint32_t a[4];
            a[0] = packh2(s[kg * 2][0],     s[kg * 2][1]);
            a[1] = packh2(s[kg * 2][2],     s[kg * 2][3]);
            a[2] = packh2(s[kg * 2 + 1][0], s[kg * 2 + 1][1]);
            a[3] = packh2(s[kg * 2 + 1][2], s[kg * 2 + 1][3]);
            #pragma unroll
            for (int vn = 0; vn < 4; vn++) {
                uint32_t bf[4];
                int row = kg * 16 + (lane & 7) + ((lane >> 3) & 1) * 8;
                int c = vn * 2 + (lane >> 4);
                ldsm4t(bf, vB + row * 128 + ((c ^ (row & 7)) * 16));
                hmma(o[vn * 2 + 0], a, bf[0], bf[1]);
                hmma(o[vn * 2 + 1], a, bf[2], bf[3]);
            }
        }
        __syncthreads();
    }

    // normalize + write to g_xh [B,S,D]
    float inv0 = 1.f / lrow0, inv1 = 1.f / lrow1;
    int m = m0 + w * 16 + (lane >> 2);
    #pragma unroll
    for (int t = 0; t < 8; t++) {
        int hd = t * 8 + (lane & 3) * 2;
        *(__half2*)&g_xh[((size_t)(b * SSQ + m)) * DDQ + h * HDQ + hd] =
            __floats2half2_rn(o[t][0] * inv0, o[t][1] * inv0);
        *(__half2*)&g_xh[((size_t)(b * SSQ + m + 8)) * DDQ + h * HDQ + hd] =
            __floats2half2_rn(o[t][2] * inv1, o[t][3] * inv1);
    }
}

// ================= elementwise / reduction kernels ===========================
__inline__ __device__ float blockReduceSum128(float val) {
    __shared__ float sh[4];
    int lane = threadIdx.x & 31, w = threadIdx.x >> 5;
    #pragma unroll
    for (int o = 16; o; o >>= 1) val += __shfl_xor_sync(0xffffffffu, val, o);
    if (lane == 0) sh[w] = val;
    __syncthreads();
    float r = sh[0] + sh[1] + sh[2] + sh[3];
    __syncthreads();
    return r;
}

__global__ void k_addpos(const float* __restrict__ x) {
    int idx = blockIdx.x * 256 + threadIdx.x;
    if (idx >= MMQ * DDQ) return;
    int c = idx & (DDQ - 1);
    int s = (idx >> 9) % SSQ;
    float inv = exp2f(-((float)(2 * c) * (1.0f / 512.0f)) * 13.2877123795494f);
    float ang = (float)s * inv;
    float pe = (c & 1) ? cosf(ang) : sinf(ang);
    g_res[idx] = x[idx] + pe;
}

// layernorm fp32 in -> fp16 out
__global__ void k_ln16(const float* __restrict__ in, __half* __restrict__ tgt,
                       const float* __restrict__ gm, const float* __restrict__ bt) {
    int row = blockIdx.x;
    int t = threadIdx.x;
    float4 v = ((const float4*)(in + (size_t)row * DDQ))[t];
    float s = v.x + v.y + v.z + v.w;
    float mean = blockReduceSum128(s) * (1.0f / DDQ);
    float dx = v.x - mean, dy = v.y - mean, dz = v.z - mean, dw = v.w - mean;
    float s2 = dx*dx + dy*dy + dz*dz + dw*dw;
    float var = blockReduceSum128(s2) * (1.0f / DDQ);
    float inv = rsqrtf(var + 1e-5f);
    int c = t * 4;
    float ox = dx * inv * gm[c+0] + bt[c+0];
    float oy = dy * inv * gm[c+1] + bt[c+1];
    float oz = dz * inv * gm[c+2] + bt[c+2];
    float ow = dw * inv * gm[c+3] + bt[c+3];
    __half2* hp = (__half2*)(tgt + (size_t)row * DDQ + c);
    hp[0] = __floats2half2_rn(ox, oy);
    hp[1] = __floats2half2_rn(oz, ow);
}

// depthwise conv (K=7, same padding), fp16 in -> fp16 out, 4 channels/thread
__global__ void k_dwconv_h(const __half* __restrict__ in,
                           const float* __restrict__ dw) {
    int idx = blockIdx.x * 256 + threadIdx.x;
    if (idx >= MMQ * 128) return;
    int c4 = (idx & 127) * 4;
    int bs = idx >> 7;
    int s = bs % SSQ, b = bs / SSQ;
    const float* w0 = dw + (c4 + 0) * KKQ;
    const float* w1 = dw + (c4 + 1) * KKQ;
    const float* w2 = dw + (c4 + 2) * KKQ;
    const float* w3 = dw + (c4 + 3) * KKQ;
    float a0 = 0.f, a1 = 0.f, a2 = 0.f, a3 = 0.f;
    #pragma unroll
    for (int k = 0; k < KKQ; k++) {
        int ss = s + k - 3;
        if (ss >= 0 && ss < SSQ) {
            uint2 raw = *(const uint2*)&in[(((size_t)b * SSQ + ss) << 9) + c4];
            __half2 h01 = *reinterpret_cast<__half2*>(&raw.x);
            __half2 h23 = *reinterpret_cast<__half2*>(&raw.y);
            float2 f01 = __half22float2(h01), f23 = __half22float2(h23);
            a0 += f01.x * w0[k]; a1 += f01.y * w1[k];
            a2 += f23.x * w2[k]; a3 += f23.y * w3[k];
        }
    }
    __half2 o01 = __floats2half2_rn(a0, a1), o23 = __floats2half2_rn(a2, a3);
    uint2 o;
    o.x = *reinterpret_cast<uint32_t*>(&o01);
    o.y = *reinterpret_cast<uint32_t*>(&o23);
    *(uint2*)&g_xh[((size_t)bs << 9) + c4] = o;
}

// single fused fp32->fp16 weight conversion for all 9 matrices (float4)
__global__ void k_f2h_all(const float* __restrict__ pw_w, const float* __restrict__ wq,
                          const float* __restrict__ wk, const float* __restrict__ wv,
                          const float* __restrict__ wo, const float* __restrict__ fw) {
    const int WSZ4 = (DDQ * DDQ) / 4;   // 65536 4-packs per matrix
    int idx4 = blockIdx.x * 256 + threadIdx.x;
    if (idx4 >= 9 * WSZ4) return;
    int seg = idx4 / WSZ4;
    int off4 = idx4 - seg * WSZ4;
    const float* src;
    if (seg < 4)      src = pw_w + (size_t)seg * DDQ * DDQ;
    else if (seg == 4) src = wq;
    else if (seg == 5) src = wk;
    else if (seg == 6) src = wv;
    else if (seg == 7) src = wo;
    else               src = fw;
    float4 v = ((const float4*)src)[off4];
    __half2 h01 = __floats2half2_rn(v.x, v.y), h23 = __floats2half2_rn(v.z, v.w);
    uint2 o;
    o.x = *reinterpret_cast<uint32_t*>(&h01);
    o.y = *reinterpret_cast<uint32_t*>(&h23);
    *(uint2*)&g_wh[((size_t)seg * DDQ * DDQ) + off4 * 4] = o;
}

// ---------------- host orchestration -----------------------------------------
extern "C" void kernel_launch(void* const* d_in, const int* in_sizes, int n_in,
                              void* d_out, int out_size) {
    const float* x    = (const float*)d_in[0];
    const int*   mask = (const int*)  d_in[1];
    const float* dw_w = (const float*)d_in[2];
    const float* pw_w = (const float*)d_in[3];
    const float* pw_b = (const float*)d_in[4];
    const float* cg   = (const float*)d_in[5];
    const float* cb   = (const float*)d_in[6];
    const float* pg   = (const float*)d_in[7];
    const float* pb   = (const float*)d_in[8];
    const float* wq   = (const float*)d_in[9];
    const float* bq   = (const float*)d_in[10];
    const float* wk   = (const float*)d_in[11];
    const float* bk   = (const float*)d_in[12];
    const float* wv   = (const float*)d_in[13];
    const float* bv   = (const float*)d_in[14];
    const float* wo   = (const float*)d_in[15];
    const float* bo   = (const float*)d_in[16];
    const float* fg   = (const float*)d_in[17];
    const float* fb   = (const float*)d_in[18];
    const float* fw   = (const float*)d_in[19];
    const float* fbi  = (const float*)d_in[20];
    float* out = (float*)d_out;

    float* p_res;
    __half *p_xh, *p_wh, *p_qh, *p_kh, *p_vh;
    cudaGetSymbolAddress((void**)&p_res, g_res);
    cudaGetSymbolAddress((void**)&p_xh,  g_xh);
    cudaGetSymbolAddress((void**)&p_wh,  g_wh);
    cudaGetSymbolAddress((void**)&p_qh,  g_qh);
    cudaGetSymbolAddress((void**)&p_kh,  g_kh);
    cudaGetSymbolAddress((void**)&p_vh,  g_vh);

    const int NELEM = MMQ * DDQ;
    const int WSZ = DDQ * DDQ;  // 262144
    dim3 dg(8, 48);             // N/64, M/128

    // 0. weights -> fp16 (one fused launch)
    k_f2h_all<<<(9 * WSZ / 4 + 255) / 256, 256>>>(pw_w, wq, wk, wv, wo, fw);

    // 1. res = x + PE ; LN -> fp16 (conv input in g_qh)
    k_addpos<<<(NELEM + 255) / 256, 256>>>(x);
    k_ln16<<<MMQ, 128>>>(p_res, p_qh, pg, pb);

    // 2. conv stack
    for (int l = 0; l < LLQ; l++) {
        k_dwconv_h<<<(MMQ * 128 + 255) / 256, 256>>>(p_qh, dw_w + l * DDQ * KKQ);
        k_gemm_h<1, 1, 0><<<dg, 256>>>(p_xh, p_wh + (size_t)l * WSZ,
                                       pw_b + l * DDQ, p_res, p_res, nullptr);
        // LN -> fp16; conv layers feed next dwconv (g_qh), last feeds QKV GEMM (g_xh)
        k_ln16<<<MMQ, 128>>>(p_res, (l < LLQ - 1) ? p_qh : p_xh,
                             cg + l * DDQ, cb + l * DDQ);
    }

    // 3. attention
    k_gemm_h<0, 0, 1><<<dg, 256>>>(p_xh, p_wh + 4 * (size_t)WSZ, bq, p_res, nullptr, p_qh);
    k_gemm_h<0, 0, 1><<<dg, 256>>>(p_xh, p_wh + 5 * (size_t)WSZ, bk, p_res, nullptr, p_kh);
    k_gemm_h<0, 0, 1><<<dg, 256>>>(p_xh, p_wh + 6 * (size_t)WSZ, bv, p_res, nullptr, p_vh);
    k_flash<<<dim3(3, BHQ), 256>>>(mask);
    k_gemm_h<0, 1, 0><<<dg, 256>>>(p_xh, p_wh + 7 * (size_t)WSZ, bo, p_res, p_res, nullptr);

    // 4. feedforward: out = relu(LN(res) @ fw^T + fb) + res
    k_ln16<<<MMQ, 128>>>(p_res, p_xh, fg, fb);
    k_gemm_h<1, 1, 0><<<dg, 256>>>(p_xh, p_wh + 8 * (size_t)WSZ, fbi, p_res, out, nullptr);
}

// round 6
// speedup vs baseline: 6.5163x; 1.1696x over previous
#include <cuda_runtime.h>
#include <cuda_fp16.h>
#include <math.h>
#include <stdint.h>

// Problem constants
#define BB   16
#define SSQ  384
#define DDQ  512
#define HHQ  8
#define HDQ  64
#define LLQ  4
#define KKQ  7
#define MMQ  (BB*SSQ)      // 6144 rows
#define BHQ  (BB*HHQ)      // 128 batch*heads

// ---------------- scratch (device globals; no allocation allowed) -----------
__device__ float g_res[MMQ*DDQ];                        // fp32 residual spine
__device__ __half g_xh[MMQ*DDQ];                        // fp16 GEMM A operand
__device__ __half g_wh[9*DDQ*DDQ];                      // fp16 weights
__device__ __half g_qh[MMQ*DDQ];                        // LN16 out (conv) / Q (attn)
__device__ __half g_kh[MMQ*DDQ];
__device__ __half g_vh[MMQ*DDQ];

// ================= low-level helpers =========================================
__device__ __forceinline__ uint32_t smem_u32(const void* p) {
    uint32_t a;
    asm("{ .reg .u64 t; cvta.to.shared.u64 t, %1; cvt.u32.u64 %0, t; }" : "=r"(a) : "l"(p));
    return a;
}
__device__ __forceinline__ void cpa16(uint32_t dst, const void* src) {
    asm volatile("cp.async.cg.shared.global [%0], [%1], 16;" :: "r"(dst), "l"(src) : "memory");
}
#define CP_COMMIT() asm volatile("cp.async.commit_group;" ::: "memory")
#define CP_WAIT(n)  asm volatile("cp.async.wait_group %0;" :: "n"(n) : "memory")

__device__ __forceinline__ void ldsm4(uint32_t* r, uint32_t addr) {
    asm volatile("ldmatrix.sync.aligned.m8n8.x4.shared.b16 {%0,%1,%2,%3}, [%4];"
                 : "=r"(r[0]), "=r"(r[1]), "=r"(r[2]), "=r"(r[3]) : "r"(addr));
}
__device__ __forceinline__ void ldsm4t(uint32_t* r, uint32_t addr) {
    asm volatile("ldmatrix.sync.aligned.m8n8.x4.trans.shared.b16 {%0,%1,%2,%3}, [%4];"
                 : "=r"(r[0]), "=r"(r[1]), "=r"(r[2]), "=r"(r[3]) : "r"(addr));
}
__device__ __forceinline__ void hmma(float* d, const uint32_t* a, uint32_t b0, uint32_t b1) {
    asm volatile(
        "mma.sync.aligned.m16n8k16.row.col.f32.f16.f16.f32 "
        "{%0,%1,%2,%3}, {%4,%5,%6,%7}, {%8,%9}, {%0,%1,%2,%3};"
        : "+f"(d[0]), "+f"(d[1]), "+f"(d[2]), "+f"(d[3])
        : "r"(a[0]), "r"(a[1]), "r"(a[2]), "r"(a[3]), "r"(b0), "r"(b1));
}
__device__ __forceinline__ uint32_t packh2(float x, float y) {
    __half2 h = __floats2half2_rn(x, y);
    return *reinterpret_cast<uint32_t*>(&h);
}

// ================= dense GEMM: Y[6144,512] = X@W^T + epilogue ================
// X fp16 [M,512], W fp16 [N,512]. BM=128 BN=64 BK=32, 256 threads
// (8 warps, 4m x 2n, warp tile 32x32), cp.async 2-stage.
template<int RELU, int ADDRES, int SCATTER>
__global__ void __launch_bounds__(256)
k_gemm_h(const __half* __restrict__ X, const __half* __restrict__ W,
         const float* __restrict__ bias, const float* __restrict__ res,
         float* __restrict__ outf, __half* __restrict__ outh) {
    __shared__ __half As[2][128 * 32];
    __shared__ __half Bs[2][64 * 32];
    const int tid = threadIdx.x, lane = tid & 31, wid = tid >> 5;
    const int wm = wid >> 1, wn = wid & 1;
    const int m0 = blockIdx.y * 128, n0 = blockIdx.x * 64;
    float acc[2][4][4] = {};

    const uint32_t aBase[2] = { smem_u32(&As[0][0]), smem_u32(&As[1][0]) };
    const uint32_t bBase[2] = { smem_u32(&Bs[0][0]), smem_u32(&Bs[1][0]) };

    // initial load kt=0 buf=0
    {
        #pragma unroll
        for (int i = 0; i < 2; i++) {
            int q = tid + i * 256; int r = q >> 2, c = q & 3;
            cpa16(aBase[0] + r * 64 + ((c ^ (r & 3)) * 16),
                  X + (size_t)(m0 + r) * DDQ + c * 8);
        }
        { int r = tid >> 2, c = tid & 3;
          cpa16(bBase[0] + r * 64 + ((c ^ (r & 3)) * 16),
                W + (size_t)(n0 + r) * DDQ + c * 8); }
        CP_COMMIT();
    }

    #pragma unroll 1
    for (int kt = 0; kt < 16; kt++) {
        int buf = kt & 1;
        if (kt < 15) {
            int nb = buf ^ 1;
            #pragma unroll
            for (int i = 0; i < 2; i++) {
                int q = tid + i * 256; int r = q >> 2, c = q & 3;
                cpa16(aBase[nb] + r * 64 + ((c ^ (r & 3)) * 16),
                      X + (size_t)(m0 + r) * DDQ + (kt + 1) * 32 + c * 8);
            }
            { int r = tid >> 2, c = tid & 3;
              cpa16(bBase[nb] + r * 64 + ((c ^ (r & 3)) * 16),
                    W + (size_t)(n0 + r) * DDQ + (kt + 1) * 32 + c * 8); }
            CP_COMMIT();
            CP_WAIT(1);
        } else {
            CP_WAIT(0);
        }
        __syncthreads();
        #pragma unroll
        for (int ks = 0; ks < 2; ks++) {
            uint32_t a[2][4], b[2][4];
            #pragma unroll
            for (int mt = 0; mt < 2; mt++) {
                int r = wm * 32 + mt * 16 + (lane & 15);
                int c = ks * 2 + (lane >> 4);
                ldsm4(a[mt], aBase[buf] + r * 64 + ((c ^ (r & 3)) * 16));
            }
            #pragma unroll
            for (int np = 0; np < 2; np++) {
                int nr = wn * 32 + np * 16 + (lane & 7) + ((lane >> 4) << 3);
                int c = ks * 2 + ((lane >> 3) & 1);
                ldsm4(b[np], bBase[buf] + nr * 64 + ((c ^ (nr & 3)) * 16));
            }
            #pragma unroll
            for (int mt = 0; mt < 2; mt++)
                #pragma unroll
                for (int nt = 0; nt < 4; nt++)
                    hmma(acc[mt][nt], a[mt], b[nt >> 1][(nt & 1) * 2], b[nt >> 1][(nt & 1) * 2 + 1]);
        }
        __syncthreads();
    }

    // epilogue
    #pragma unroll
    for (int mt = 0; mt < 2; mt++) {
        int r = m0 + wm * 32 + mt * 16 + (lane >> 2);
        #pragma unroll
        for (int nt = 0; nt < 4; nt++) {
            int cl = wn * 32 + nt * 8 + (lane & 3) * 2;
            int n = n0 + cl;
            float b0 = bias[n], b1 = bias[n + 1];
            float v00 = acc[mt][nt][0] + b0, v01 = acc[mt][nt][1] + b1;
            float v10 = acc[mt][nt][2] + b0, v11 = acc[mt][nt][3] + b1;
            if (RELU) {
                v00 = fmaxf(v00, 0.f); v01 = fmaxf(v01, 0.f);
                v10 = fmaxf(v10, 0.f); v11 = fmaxf(v11, 0.f);
            }
            if (ADDRES) {
                float2 r0 = *(const float2*)&res[(size_t)r * DDQ + n];
                float2 r1 = *(const float2*)&res[(size_t)(r + 8) * DDQ + n];
                v00 += r0.x; v01 += r0.y; v10 += r1.x; v11 += r1.y;
            }
            if (SCATTER) {
                int h = n >> 6, hd = n & 63;
                int b_ = r / SSQ, s = r % SSQ;
                *(__half2*)&outh[(((size_t)(b_ * HHQ + h) * SSQ + s) << 6) + hd] =
                    __floats2half2_rn(v00, v01);
                int b2 = (r + 8) / SSQ, s2 = (r + 8) % SSQ;
                *(__half2*)&outh[(((size_t)(b2 * HHQ + h) * SSQ + s2) << 6) + hd] =
                    __floats2half2_rn(v10, v11);
            } else {
                *(float2*)&outf[(size_t)r * DDQ + n] = make_float2(v00, v01);
                *(float2*)&outf[(size_t)(r + 8) * DDQ + n] = make_float2(v10, v11);
            }
        }
    }
}

// ================= flash attention ==========================================
// One block = (q-tile of 128 rows) x (one bh). 8 warps, warp = 16 q-rows x all cols.
__global__ void __launch_bounds__(256)
k_flash(const int* __restrict__ mask) {
    __shared__ __half Qs[128 * 64];
    __shared__ __half Ks[128 * 64];
    __shared__ __half Vs[128 * 64];
    __shared__ int misk[128];
    const int bh = blockIdx.y, b = bh >> 3, h = bh & 7;
    const __half* Q = g_qh + (size_t)bh * SSQ * HDQ;
    const __half* K = g_kh + (size_t)bh * SSQ * HDQ;
    const __half* V = g_vh + (size_t)bh * SSQ * HDQ;
    const int m0 = blockIdx.x * 128;
    const int tid = threadIdx.x, lane = tid & 31, w = tid >> 5;
    const uint32_t qB = smem_u32(Qs), kB = smem_u32(Ks), vB = smem_u32(Vs);

    #pragma unroll
    for (int i = 0; i < 4; i++) {
        int q = tid + i * 256; int r = q >> 3, c = q & 7;
        cpa16(qB + r * 128 + ((c ^ (r & 7)) * 16), Q + (size_t)(m0 + r) * HDQ + c * 8);
    }

    float o[8][4] = {};
    float mrow0 = -3.0e38f, mrow1 = -3.0e38f, lrow0 = 0.f, lrow1 = 0.f;
    const float LOG2E = 1.4426950408889634f;

    #pragma unroll 1
    for (int kc = 0; kc < 3; kc++) {
        if (tid < 128) misk[tid] = mask[b * SSQ + kc * 128 + tid];
        #pragma unroll
        for (int i = 0; i < 4; i++) {
            int q = tid + i * 256; int r = q >> 3, c = q & 7;
            cpa16(kB + r * 128 + ((c ^ (r & 7)) * 16),
                  K + (size_t)(kc * 128 + r) * HDQ + c * 8);
            cpa16(vB + r * 128 + ((c ^ (r & 7)) * 16),
                  V + (size_t)(kc * 128 + r) * HDQ + c * 8);
        }
        CP_COMMIT(); CP_WAIT(0);
        __syncthreads();

        float s[16][4] = {};
        #pragma unroll
        for (int ks = 0; ks < 4; ks++) {
            uint32_t a[4];
            { int r = w * 16 + (lane & 15);
              int c = ks * 2 + (lane >> 4);
              ldsm4(a, qB + r * 128 + ((c ^ (r & 7)) * 16)); }
            #pragma unroll
            for (int np = 0; np < 8; np++) {
                uint32_t bf[4];
                int nr = np * 16 + (lane & 7) + ((lane >> 4) << 3);
                int c = ks * 2 + ((lane >> 3) & 1);
                ldsm4(bf, kB + nr * 128 + ((c ^ (nr & 7)) * 16));
                hmma(s[np * 2 + 0], a, bf[0], bf[1]);
                hmma(s[np * 2 + 1], a, bf[2], bf[3]);
            }
        }

        float mx0 = -3.0e38f, mx1 = -3.0e38f;
        #pragma unroll
        for (int nt = 0; nt < 16; nt++) {
            int nc = nt * 8 + (lane & 3) * 2;
            int f0 = misk[nc], f1 = misk[nc + 1];
            s[nt][0] = f0 ? -1e10f : s[nt][0] * 0.125f;
            s[nt][1] = f1 ? -1e10f : s[nt][1] * 0.125f;
            s[nt][2] = f0 ? -1e10f : s[nt][2] * 0.125f;
            s[nt][3] = f1 ? -1e10f : s[nt][3] * 0.125f;
            mx0 = fmaxf(mx0, fmaxf(s[nt][0], s[nt][1]));
            mx1 = fmaxf(mx1, fmaxf(s[nt][2], s[nt][3]));
        }
        #pragma unroll
        for (int of = 1; of <= 2; of <<= 1) {
            mx0 = fmaxf(mx0, __shfl_xor_sync(0xffffffffu, mx0, of));
            mx1 = fmaxf(mx1, __shfl_xor_sync(0xffffffffu, mx1, of));
        }
        float mn0 = fmaxf(mrow0, mx0), mn1 = fmaxf(mrow1, mx1);
        float al0 = exp2f((mrow0 - mn0) * LOG2E);
        float al1 = exp2f((mrow1 - mn1) * LOG2E);
        mrow0 = mn0; mrow1 = mn1;

        float sum0 = 0.f, sum1 = 0.f;
        #pragma unroll
        for (int nt = 0; nt < 16; nt++) {
            s[nt][0] = exp2f((s[nt][0] - mn0) * LOG2E);
            s[nt][1] = exp2f((s[nt][1] - mn0) * LOG2E);
            s[nt][2] = exp2f((s[nt][2] - mn1) * LOG2E);
            s[nt][3] = exp2f((s[nt][3] - mn1) * LOG2E);
            sum0 += s[nt][0] + s[nt][1];
            sum1 += s[nt][2] + s[nt][3];
        }
        #pragma unroll
        for (int of = 1; of <= 2; of <<= 1) {
            sum0 += __shfl_xor_sync(0xffffffffu, sum0, of);
            sum1 += __shfl_xor_sync(0xffffffffu, sum1, of);
        }
        lrow0 = lrow0 * al0 + sum0;
        lrow1 = lrow1 * al1 + sum1;

        #pragma unroll
        for (int t = 0; t < 8; t++) {
            o[t][0] *= al0; o[t][1] *= al0; o[t][2] *= al1; o[t][3] *= al1;
        }

        #pragma unroll
        for (int kg = 0; kg < 8; kg++) {
            uint32_t a[4];
            a[0] = packh2(s[kg * 2][0],     s[kg * 2][1]);
            a[1] = packh2(s[kg * 2][2],     s[kg * 2][3]);
            a[2] = packh2(s[kg * 2 + 1][0], s[kg * 2 + 1][1]);
            a[3] = packh2(s[kg * 2 + 1][2], s[kg * 2 + 1][3]);
            #pragma unroll
            for (int vn = 0; vn < 4; vn++) {
                uint32_t bf[4];
                int row = kg * 16 + (lane & 7) + ((lane >> 3) & 1) * 8;
                int c = vn * 2 + (lane >> 4);
                ldsm4t(bf, vB + row * 128 + ((c ^ (row & 7)) * 16));
                hmma(o[vn * 2 + 0], a, bf[0], bf[1]);
                hmma(o[vn * 2 + 1], a, bf[2], bf[3]);
            }
        }
        __syncthreads();
    }

    float inv0 = 1.f / lrow0, inv1 = 1.f / lrow1;
    int m = m0 + w * 16 + (lane >> 2);
    #pragma unroll
    for (int t = 0; t < 8; t++) {
        int hd = t * 8 + (lane & 3) * 2;
        *(__half2*)&g_xh[((size_t)(b * SSQ + m)) * DDQ + h * HDQ + hd] =
            __floats2half2_rn(o[t][0] * inv0, o[t][1] * inv0);
        *(__half2*)&g_xh[((size_t)(b * SSQ + m + 8)) * DDQ + h * HDQ + hd] =
            __floats2half2_rn(o[t][2] * inv1, o[t][3] * inv1);
    }
}

// ================= elementwise / reduction kernels ===========================
__inline__ __device__ float blockReduceSum128(float val) {
    __shared__ float sh[4];
    int lane = threadIdx.x & 31, w = threadIdx.x >> 5;
    #pragma unroll
    for (int o = 16; o; o >>= 1) val += __shfl_xor_sync(0xffffffffu, val, o);
    if (lane == 0) sh[w] = val;
    __syncthreads();
    float r = sh[0] + sh[1] + sh[2] + sh[3];
    __syncthreads();
    return r;
}

// fused: res = x + PE; tgt(fp16) = LN(res)*g + b.  one block (128 thr) per row.
__global__ void k_addpos_ln(const float* __restrict__ x, __half* __restrict__ tgt,
                            const float* __restrict__ gm, const float* __restrict__ bt) {
    int row = blockIdx.x;
    int s = row % SSQ;
    int t = threadIdx.x;
    int c = t * 4;
    float4 v = ((const float4*)(x + (size_t)row * DDQ))[t];
    float pe[4];
    #pragma unroll
    for (int i = 0; i < 4; i++) {
        int ci = c + i;
        float inv = exp2f(-((float)(2 * ci) * (1.0f / 512.0f)) * 13.2877123795494f);
        float ang = (float)s * inv;
        pe[i] = (ci & 1) ? cosf(ang) : sinf(ang);
    }
    v.x += pe[0]; v.y += pe[1]; v.z += pe[2]; v.w += pe[3];
    ((float4*)(g_res + (size_t)row * DDQ))[t] = v;

    float sm = v.x + v.y + v.z + v.w;
    float mean = blockReduceSum128(sm) * (1.0f / DDQ);
    float dx = v.x - mean, dy = v.y - mean, dz = v.z - mean, dw = v.w - mean;
    float s2 = dx*dx + dy*dy + dz*dz + dw*dw;
    float var = blockReduceSum128(s2) * (1.0f / DDQ);
    float inv = rsqrtf(var + 1e-5f);
    float ox = dx * inv * gm[c+0] + bt[c+0];
    float oy = dy * inv * gm[c+1] + bt[c+1];
    float oz = dz * inv * gm[c+2] + bt[c+2];
    float ow = dw * inv * gm[c+3] + bt[c+3];
    __half2* hp = (__half2*)(tgt + (size_t)row * DDQ + c);
    hp[0] = __floats2half2_rn(ox, oy);
    hp[1] = __floats2half2_rn(oz, ow);
}

// layernorm fp32 in -> fp16 out
__global__ void k_ln16(const float* __restrict__ in, __half* __restrict__ tgt,
                       const float* __restrict__ gm, const float* __restrict__ bt) {
    int row = blockIdx.x;
    int t = threadIdx.x;
    float4 v = ((const float4*)(in + (size_t)row * DDQ))[t];
    float s = v.x + v.y + v.z + v.w;
    float mean = blockReduceSum128(s) * (1.0f / DDQ);
    float dx = v.x - mean, dy = v.y - mean, dz = v.z - mean, dw = v.w - mean;
    float s2 = dx*dx + dy*dy + dz*dz + dw*dw;
    float var = blockReduceSum128(s2) * (1.0f / DDQ);
    float inv = rsqrtf(var + 1e-5f);
    int c = t * 4;
    float ox = dx * inv * gm[c+0] + bt[c+0];
    float oy = dy * inv * gm[c+1] + bt[c+1];
    float oz = dz * inv * gm[c+2] + bt[c+2];
    float ow = dw * inv * gm[c+3] + bt[c+3];
    __half2* hp = (__half2*)(tgt + (size_t)row * DDQ + c);
    hp[0] = __floats2half2_rn(ox, oy);
    hp[1] = __floats2half2_rn(oz, ow);
}

// depthwise conv (K=7, same padding), fp16 in/out.
// thread = 4 channels x 4 consecutive s positions (10 row-loads / 16 outputs).
__global__ void __launch_bounds__(256)
k_dwconv_h(const __half* __restrict__ in, const float* __restrict__ dw) {
    int idx = blockIdx.x * 256 + threadIdx.x;
    if (idx >= (MMQ / 4) * 128) return;
    int c4 = (idx & 127) * 4;
    int bs4 = idx >> 7;                 // 0..1535
    const int SC = SSQ / 4;             // 96
    int b = bs4 / SC, s0 = (bs4 - b * SC) * 4;

    float w[4][KKQ];
    #pragma unroll
    for (int i = 0; i < 4; i++)
        #pragma unroll
        for (int k = 0; k < KKQ; k++)
            w[i][k] = dw[(c4 + i) * KKQ + k];

    float acc[4][4] = {};
    #pragma unroll
    for (int r = 0; r < 10; r++) {
        int ss = s0 - 3 + r;
        if (ss >= 0 && ss < SSQ) {
            uint2 raw = *(const uint2*)&in[(((size_t)b * SSQ + ss) << 9) + c4];
            __half2 h01 = *reinterpret_cast<__half2*>(&raw.x);
            __half2 h23 = *reinterpret_cast<__half2*>(&raw.y);
            float2 f01 = __half22float2(h01), f23 = __half22float2(h23);
            #pragma unroll
            for (int j = 0; j < 4; j++) {
                int t = r - j;
                if (t >= 0 && t < KKQ) {
                    acc[j][0] += f01.x * w[0][t];
                    acc[j][1] += f01.y * w[1][t];
                    acc[j][2] += f23.x * w[2][t];
                    acc[j][3] += f23.y * w[3][t];
                }
            }
        }
    }
    #pragma unroll
    for (int j = 0; j < 4; j++) {
        __half2 o01 = __floats2half2_rn(acc[j][0], acc[j][1]);
        __half2 o23 = __floats2half2_rn(acc[j][2], acc[j][3]);
        uint2 o;
        o.x = *reinterpret_cast<uint32_t*>(&o01);
        o.y = *reinterpret_cast<uint32_t*>(&o23);
        *(uint2*)&g_xh[(((size_t)b * SSQ + s0 + j) << 9) + c4] = o;
    }
}

// single fused fp32->fp16 weight conversion for all 9 matrices (float4)
__global__ void k_f2h_all(const float* __restrict__ pw_w, const float* __restrict__ wq,
                          const float* __restrict__ wk, const float* __restrict__ wv,
                          const float* __restrict__ wo, const float* __restrict__ fw) {
    const int WSZ4 = (DDQ * DDQ) / 4;   // 65536 4-packs per matrix
    int idx4 = blockIdx.x * 256 + threadIdx.x;
    if (idx4 >= 9 * WSZ4) return;
    int seg = idx4 / WSZ4;
    int off4 = idx4 - seg * WSZ4;
    const float* src;
    if (seg < 4)      src = pw_w + (size_t)seg * DDQ * DDQ;
    else if (seg == 4) src = wq;
    else if (seg == 5) src = wk;
    else if (seg == 6) src = wv;
    else if (seg == 7) src = wo;
    else               src = fw;
    float4 v = ((const float4*)src)[off4];
    __half2 h01 = __floats2half2_rn(v.x, v.y), h23 = __floats2half2_rn(v.z, v.w);
    uint2 o;
    o.x = *reinterpret_cast<uint32_t*>(&h01);
    o.y = *reinterpret_cast<uint32_t*>(&h23);
    *(uint2*)&g_wh[((size_t)seg * DDQ * DDQ) + off4 * 4] = o;
}

// ---------------- host orchestration -----------------------------------------
extern "C" void kernel_launch(void* const* d_in, const int* in_sizes, int n_in,
                              void* d_out, int out_size) {
    const float* x    = (const float*)d_in[0];
    const int*   mask = (const int*)  d_in[1];
    const float* dw_w = (const float*)d_in[2];
    const float* pw_w = (const float*)d_in[3];
    const float* pw_b = (const float*)d_in[4];
    const float* cg   = (const float*)d_in[5];
    const float* cb   = (const float*)d_in[6];
    const float* pg   = (const float*)d_in[7];
    const float* pb   = (const float*)d_in[8];
    const float* wq   = (const float*)d_in[9];
    const float* bq   = (const float*)d_in[10];
    const float* wk   = (const float*)d_in[11];
    const float* bk   = (const float*)d_in[12];
    const float* wv   = (const float*)d_in[13];
    const float* bv   = (const float*)d_in[14];
    const float* wo   = (const float*)d_in[15];
    const float* bo   = (const float*)d_in[16];
    const float* fg   = (const float*)d_in[17];
    const float* fb   = (const float*)d_in[18];
    const float* fw   = (const float*)d_in[19];
    const float* fbi  = (const float*)d_in[20];
    float* out = (float*)d_out;

    float* p_res;
    __half *p_xh, *p_wh, *p_qh, *p_kh, *p_vh;
    cudaGetSymbolAddress((void**)&p_res, g_res);
    cudaGetSymbolAddress((void**)&p_xh,  g_xh);
    cudaGetSymbolAddress((void**)&p_wh,  g_wh);
    cudaGetSymbolAddress((void**)&p_qh,  g_qh);
    cudaGetSymbolAddress((void**)&p_kh,  g_kh);
    cudaGetSymbolAddress((void**)&p_vh,  g_vh);

    const int WSZ = DDQ * DDQ;  // 262144
    dim3 dg(8, 48);             // N/64, M/128

    // 0. weights -> fp16 (one fused launch)
    k_f2h_all<<<(9 * WSZ / 4 + 255) / 256, 256>>>(pw_w, wq, wk, wv, wo, fw);

    // 1. res = x + PE ; LN -> fp16 (conv input in g_qh), fused
    k_addpos_ln<<<MMQ, 128>>>(x, p_qh, pg, pb);

    // 2. conv stack
    for (int l = 0; l < LLQ; l++) {
        k_dwconv_h<<<(MMQ / 4) * 128 / 256, 256>>>(p_qh, dw_w + l * DDQ * KKQ);
        k_gemm_h<1, 1, 0><<<dg, 256>>>(p_xh, p_wh + (size_t)l * WSZ,
                                       pw_b + l * DDQ, p_res, p_res, nullptr);
        k_ln16<<<MMQ, 128>>>(p_res, (l < LLQ - 1) ? p_qh : p_xh,
                             cg + l * DDQ, cb + l * DDQ);
    }

    // 3. attention
    k_gemm_h<0, 0, 1><<<dg, 256>>>(p_xh, p_wh + 4 * (size_t)WSZ, bq, p_res, nullptr, p_qh);
    k_gemm_h<0, 0, 1><<<dg, 256>>>(p_xh, p_wh + 5 * (size_t)WSZ, bk, p_res, nullptr, p_kh);
    k_gemm_h<0, 0, 1><<<dg, 256>>>(p_xh, p_wh + 6 * (size_t)WSZ, bv, p_res, nullptr, p_vh);
    k_flash<<<dim3(3, BHQ), 256>>>(mask);
    k_gemm_h<0, 1, 0><<<dg, 256>>>(p_xh, p_wh + 7 * (size_t)WSZ, bo, p_res, p_res, nullptr);

    // 4. feedforward: out = relu(LN(res) @ fw^T + fb) + res
    k_ln16<<<MMQ, 128>>>(p_res, p_xh, fg, fb);
    k_gemm_h<1, 1, 0><<<dg, 256>>>(p_xh, p_wh + 8 * (size_t)WSZ, fbi, p_res, out, nullptr);
}

// round 7
// speedup vs baseline: 6.6573x; 1.0216x over previous
#include <cuda_runtime.h>
#include <cuda_fp16.h>
#include <math.h>
#include <stdint.h>

// Problem constants
#define BB   16
#define SSQ  384
#define DDQ  512
#define HHQ  8
#define HDQ  64
#define LLQ  4
#define KKQ  7
#define MMQ  (BB*SSQ)      // 6144 rows
#define BHQ  (BB*HHQ)      // 128 batch*heads

// ---------------- scratch (device globals; no allocation allowed) -----------
__device__ float g_res[MMQ*DDQ];                        // fp32 residual spine
__device__ __half g_xh[MMQ*DDQ];                        // fp16 GEMM A operand
__device__ __half g_wh[9*DDQ*DDQ];                      // fp16 weights
__device__ __half g_qh[MMQ*DDQ];                        // LN16 out (conv input)
__device__ __half g_qkv[3*MMQ*DDQ];                     // fused QKV, head-major

// ================= low-level helpers =========================================
__device__ __forceinline__ uint32_t smem_u32(const void* p) {
    uint32_t a;
    asm("{ .reg .u64 t; cvta.to.shared.u64 t, %1; cvt.u32.u64 %0, t; }" : "=r"(a) : "l"(p));
    return a;
}
__device__ __forceinline__ void cpa16(uint32_t dst, const void* src) {
    asm volatile("cp.async.cg.shared.global [%0], [%1], 16;" :: "r"(dst), "l"(src) : "memory");
}
#define CP_COMMIT() asm volatile("cp.async.commit_group;" ::: "memory")
#define CP_WAIT(n)  asm volatile("cp.async.wait_group %0;" :: "n"(n) : "memory")

__device__ __forceinline__ void ldsm4(uint32_t* r, uint32_t addr) {
    asm volatile("ldmatrix.sync.aligned.m8n8.x4.shared.b16 {%0,%1,%2,%3}, [%4];"
                 : "=r"(r[0]), "=r"(r[1]), "=r"(r[2]), "=r"(r[3]) : "r"(addr));
}
__device__ __forceinline__ void ldsm4t(uint32_t* r, uint32_t addr) {
    asm volatile("ldmatrix.sync.aligned.m8n8.x4.trans.shared.b16 {%0,%1,%2,%3}, [%4];"
                 : "=r"(r[0]), "=r"(r[1]), "=r"(r[2]), "=r"(r[3]) : "r"(addr));
}
__device__ __forceinline__ void hmma(float* d, const uint32_t* a, uint32_t b0, uint32_t b1) {
    asm volatile(
        "mma.sync.aligned.m16n8k16.row.col.f32.f16.f16.f32 "
        "{%0,%1,%2,%3}, {%4,%5,%6,%7}, {%8,%9}, {%0,%1,%2,%3};"
        : "+f"(d[0]), "+f"(d[1]), "+f"(d[2]), "+f"(d[3])
        : "r"(a[0]), "r"(a[1]), "r"(a[2]), "r"(a[3]), "r"(b0), "r"(b1));
}
__device__ __forceinline__ uint32_t packh2(float x, float y) {
    __half2 h = __floats2half2_rn(x, y);
    return *reinterpret_cast<uint32_t*>(&h);
}

// ================= dense GEMM: Y[6144,N] = X@W^T + epilogue ==================
// X fp16 [M,512], W fp16 [N,512]. BM=128 BN=64 BK=32, 256 threads
// (8 warps, 4m x 2n, warp tile 32x32), cp.async 3-stage, 1 sync/iter.
// SCATTER=1: fused QKV (N=1536), bias selected by n0>>9, out -> g_qkv head-major.
template<int RELU, int ADDRES, int SCATTER>
__global__ void __launch_bounds__(256)
k_gemm_h(const __half* __restrict__ X, const __half* __restrict__ W,
         const float* __restrict__ bias, const float* __restrict__ bias2,
         const float* __restrict__ bias3, const float* __restrict__ res,
         float* __restrict__ outf, __half* __restrict__ outh) {
    __shared__ __half As[3][128 * 32];
    __shared__ __half Bs[3][64 * 32];
    const int tid = threadIdx.x, lane = tid & 31, wid = tid >> 5;
    const int wm = wid >> 1, wn = wid & 1;
    const int m0 = blockIdx.y * 128, n0 = blockIdx.x * 64;
    float acc[2][4][4] = {};

    const uint32_t aB[3] = { smem_u32(&As[0][0]), smem_u32(&As[1][0]), smem_u32(&As[2][0]) };
    const uint32_t bB[3] = { smem_u32(&Bs[0][0]), smem_u32(&Bs[1][0]), smem_u32(&Bs[2][0]) };

    auto load_stage = [&](int kt, int st) {
        #pragma unroll
        for (int i = 0; i < 2; i++) {
            int q = tid + i * 256; int r = q >> 2, c = q & 3;
            cpa16(aB[st] + r * 64 + ((c ^ (r & 3)) * 16),
                  X + (size_t)(m0 + r) * DDQ + kt * 32 + c * 8);
        }
        { int r = tid >> 2, c = tid & 3;
          cpa16(bB[st] + r * 64 + ((c ^ (r & 3)) * 16),
                W + (size_t)(n0 + r) * DDQ + kt * 32 + c * 8); }
        CP_COMMIT();
    };

    load_stage(0, 0);
    load_stage(1, 1);

    #pragma unroll 1
    for (int kt = 0; kt < 16; kt++) {
        int st = kt % 3;
        if (kt < 15) { CP_WAIT(1); } else { CP_WAIT(0); }
        __syncthreads();
        if (kt + 2 < 16) load_stage(kt + 2, (kt + 2) % 3);

        // fragment prefetch: all 8 ldmatrix first (independent), then 32 hmma
        uint32_t a[2][2][4], bfr[2][2][4];
        #pragma unroll
        for (int ks = 0; ks < 2; ks++) {
            #pragma unroll
            for (int mt = 0; mt < 2; mt++) {
                int r = wm * 32 + mt * 16 + (lane & 15);
                int c = ks * 2 + (lane >> 4);
                ldsm4(a[ks][mt], aB[st] + r * 64 + ((c ^ (r & 3)) * 16));
            }
            #pragma unroll
            for (int np = 0; np < 2; np++) {
                int nr = wn * 32 + np * 16 + (lane & 7) + ((lane >> 4) << 3);
                int c = ks * 2 + ((lane >> 3) & 1);
                ldsm4(bfr[ks][np], bB[st] + nr * 64 + ((c ^ (nr & 3)) * 16));
            }
        }
        #pragma unroll
        for (int ks = 0; ks < 2; ks++)
            #pragma unroll
            for (int mt = 0; mt < 2; mt++)
                #pragma unroll
                for (int nt = 0; nt < 4; nt++)
                    hmma(acc[mt][nt], a[ks][mt],
                         bfr[ks][nt >> 1][(nt & 1) * 2], bfr[ks][nt >> 1][(nt & 1) * 2 + 1]);
    }

    // epilogue
    const int mat = n0 >> 9;          // QKV: which matrix this block serves
    const int col0 = n0 & 511;
    const float* bp = SCATTER ? ((mat == 0) ? bias : ((mat == 1) ? bias2 : bias3)) : bias;
    __half* ob = SCATTER ? (outh + (size_t)mat * MMQ * DDQ) : outh;
    #pragma unroll
    for (int mt = 0; mt < 2; mt++) {
        int r = m0 + wm * 32 + mt * 16 + (lane >> 2);
        #pragma unroll
        for (int nt = 0; nt < 4; nt++) {
            int cl = wn * 32 + nt * 8 + (lane & 3) * 2;
            int col = SCATTER ? (col0 + cl) : 0;
            int n = n0 + cl;
            float b0, b1;
            if (SCATTER) { b0 = bp[col]; b1 = bp[col + 1]; }
            else         { b0 = bp[n];   b1 = bp[n + 1]; }
            float v00 = acc[mt][nt][0] + b0, v01 = acc[mt][nt][1] + b1;
            float v10 = acc[mt][nt][2] + b0, v11 = acc[mt][nt][3] + b1;
            if (RELU) {
                v00 = fmaxf(v00, 0.f); v01 = fmaxf(v01, 0.f);
                v10 = fmaxf(v10, 0.f); v11 = fmaxf(v11, 0.f);
            }
            if (ADDRES) {
                float2 r0 = *(const float2*)&res[(size_t)r * DDQ + n];
                float2 r1 = *(const float2*)&res[(size_t)(r + 8) * DDQ + n];
                v00 += r0.x; v01 += r0.y; v10 += r1.x; v11 += r1.y;
            }
            if (SCATTER) {
                int h = col >> 6, hd = col & 63;
                int b_ = r / SSQ, s = r % SSQ;
                *(__half2*)&ob[(((size_t)(b_ * HHQ + h) * SSQ + s) << 6) + hd] =
                    __floats2half2_rn(v00, v01);
                int b2 = (r + 8) / SSQ, s2 = (r + 8) % SSQ;
                *(__half2*)&ob[(((size_t)(b2 * HHQ + h) * SSQ + s2) << 6) + hd] =
                    __floats2half2_rn(v10, v11);
            } else {
                *(float2*)&outf[(size_t)r * DDQ + n] = make_float2(v00, v01);
                *(float2*)&outf[(size_t)(r + 8) * DDQ + n] = make_float2(v10, v11);
            }
        }
    }
}

// ================= flash attention ==========================================
// One block = (q-tile of 128 rows) x (one bh). 8 warps, warp = 16 q-rows x all cols.
__global__ void __launch_bounds__(256)
k_flash(const int* __restrict__ mask) {
    __shared__ __half Qs[128 * 64];
    __shared__ __half Ks[128 * 64];
    __shared__ __half Vs[128 * 64];
    __shared__ int misk[128];
    const int bh = blockIdx.y, b = bh >> 3, h = bh & 7;
    const __half* Q = g_qkv + (size_t)bh * SSQ * HDQ;
    const __half* K = g_qkv + (size_t)MMQ * DDQ + (size_t)bh * SSQ * HDQ;
    const __half* V = g_qkv + 2 * (size_t)MMQ * DDQ + (size_t)bh * SSQ * HDQ;
    const int m0 = blockIdx.x * 128;
    const int tid = threadIdx.x, lane = tid & 31, w = tid >> 5;
    const uint32_t qB = smem_u32(Qs), kB = smem_u32(Ks), vB = smem_u32(Vs);

    #pragma unroll
    for (int i = 0; i < 4; i++) {
        int q = tid + i * 256; int r = q >> 3, c = q & 7;
        cpa16(qB + r * 128 + ((c ^ (r & 7)) * 16), Q + (size_t)(m0 + r) * HDQ + c * 8);
    }

    float o[8][4] = {};
    float mrow0 = -3.0e38f, mrow1 = -3.0e38f, lrow0 = 0.f, lrow1 = 0.f;
    const float LOG2E = 1.4426950408889634f;

    #pragma unroll 1
    for (int kc = 0; kc < 3; kc++) {
        if (tid < 128) misk[tid] = mask[b * SSQ + kc * 128 + tid];
        #pragma unroll
        for (int i = 0; i < 4; i++) {
            int q = tid + i * 256; int r = q >> 3, c = q & 7;
            cpa16(kB + r * 128 + ((c ^ (r & 7)) * 16),
                  K + (size_t)(kc * 128 + r) * HDQ + c * 8);
            cpa16(vB + r * 128 + ((c ^ (r & 7)) * 16),
                  V + (size_t)(kc * 128 + r) * HDQ + c * 8);
        }
        CP_COMMIT(); CP_WAIT(0);
        __syncthreads();

        float s[16][4] = {};
        #pragma unroll
        for (int ks = 0; ks < 4; ks++) {
            uint32_t a[4];
            { int r = w * 16 + (lane & 15);
              int c = ks * 2 + (lane >> 4);
              ldsm4(a, qB + r * 128 + ((c ^ (r & 7)) * 16)); }
            #pragma unroll
            for (int np = 0; np < 8; np++) {
                uint32_t bf[4];
                int nr = np * 16 + (lane & 7) + ((lane >> 4) << 3);
                int c = ks * 2 + ((lane >> 3) & 1);
                ldsm4(bf, kB + nr * 128 + ((c ^ (nr & 7)) * 16));
                hmma(s[np * 2 + 0], a, bf[0], bf[1]);
                hmma(s[np * 2 + 1], a, bf[2], bf[3]);
            }
        }

        float mx0 = -3.0e38f, mx1 = -3.0e38f;
        #pragma unroll
        for (int nt = 0; nt < 16; nt++) {
            int nc = nt * 8 + (lane & 3) * 2;
            int f0 = misk[nc], f1 = misk[nc + 1];
            s[nt][0] = f0 ? -1e10f : s[nt][0] * 0.125f;
            s[nt][1] = f1 ? -1e10f : s[nt][1] * 0.125f;
            s[nt][2] = f0 ? -1e10f : s[nt][2] * 0.125f;
            s[nt][3] = f1 ? -1e10f : s[nt][3] * 0.125f;
            mx0 = fmaxf(mx0, fmaxf(s[nt][0], s[nt][1]));
            mx1 = fmaxf(mx1, fmaxf(s[nt][2], s[nt][3]));
        }
        #pragma unroll
        for (int of = 1; of <= 2; of <<= 1) {
            mx0 = fmaxf(mx0, __shfl_xor_sync(0xffffffffu, mx0, of));
            mx1 = fmaxf(mx1, __shfl_xor_sync(0xffffffffu, mx1, of));
        }
        float mn0 = fmaxf(mrow0, mx0), mn1 = fmaxf(mrow1, mx1);
        float al0 = exp2f((mrow0 - mn0) * LOG2E);
        float al1 = exp2f((mrow1 - mn1) * LOG2E);
        mrow0 = mn0; mrow1 = mn1;

        float sum0 = 0.f, sum1 = 0.f;
        #pragma unroll
        for (int nt = 0; nt < 16; nt++) {
            s[nt][0] = exp2f((s[nt][0] - mn0) * LOG2E);
            s[nt][1] = exp2f((s[nt][1] - mn0) * LOG2E);
            s[nt][2] = exp2f((s[nt][2] - mn1) * LOG2E);
            s[nt][3] = exp2f((s[nt][3] - mn1) * LOG2E);
            sum0 += s[nt][0] + s[nt][1];
            sum1 += s[nt][2] + s[nt][3];
        }
        #pragma unroll
        for (int of = 1; of <= 2; of <<= 1) {
            sum0 += __shfl_xor_sync(0xffffffffu, sum0, of);
            sum1 += __shfl_xor_sync(0xffffffffu, sum1, of);
        }
        lrow0 = lrow0 * al0 + sum0;
        lrow1 = lrow1 * al1 + sum1;

        #pragma unroll
        for (int t = 0; t < 8; t++) {
            o[t][0] *= al0; o[t][1] *= al0; o[t][2] *= al1; o[t][3] *= al1;
        }

        #pragma unroll
        for (int kg = 0; kg < 8; kg++) {
            uint32_t a[4];
            a[0] = packh2(s[kg * 2][0],     s[kg * 2][1]);
            a[1] = packh2(s[kg * 2][2],     s[kg * 2][3]);
            a[2] = packh2(s[kg * 2 + 1][0], s[kg * 2 + 1][1]);
            a[3] = packh2(s[kg * 2 + 1][2], s[kg * 2 + 1][3]);
            #pragma unroll
            for (int vn = 0; vn < 4; vn++) {
                uint32_t bf[4];
                int row = kg * 16 + (lane & 7) + ((lane >> 3) & 1) * 8;
                int c = vn * 2 + (lane >> 4);
                ldsm4t(bf, vB + row * 128 + ((c ^ (row & 7)) * 16));
                hmma(o[vn * 2 + 0], a, bf[0], bf[1]);
                hmma(o[vn * 2 + 1], a, bf[2], bf[3]);
            }
        }
        __syncthreads();
    }

    float inv0 = 1.f / lrow0, inv1 = 1.f / lrow1;
    int m = m0 + w * 16 + (lane >> 2);
    #pragma unroll
    for (int t = 0; t < 8; t++) {
        int hd = t * 8 + (lane & 3) * 2;
        *(__half2*)&g_xh[((size_t)(b * SSQ + m)) * DDQ + h * HDQ + hd] =
            __floats2half2_rn(o[t][0] * inv0, o[t][1] * inv0);
        *(__half2*)&g_xh[((size_t)(b * SSQ + m + 8)) * DDQ + h * HDQ + hd] =
            __floats2half2_rn(o[t][2] * inv1, o[t][3] * inv1);
    }
}

// ================= elementwise / reduction kernels ===========================
__inline__ __device__ float blockReduceSum128(float val) {
    __shared__ float sh[4];
    int lane = threadIdx.x & 31, w = threadIdx.x >> 5;
    #pragma unroll
    for (int o = 16; o; o >>= 1) val += __shfl_xor_sync(0xffffffffu, val, o);
    if (lane == 0) sh[w] = val;
    __syncthreads();
    float r = sh[0] + sh[1] + sh[2] + sh[3];
    __syncthreads();
    return r;
}

// fused: res = x + PE; tgt(fp16) = LN(res)*g + b.  one block (128 thr) per row.
__global__ void k_addpos_ln(const float* __restrict__ x, __half* __restrict__ tgt,
                            const float* __restrict__ gm, const float* __restrict__ bt) {
    int row = blockIdx.x;
    int s = row % SSQ;
    int t = threadIdx.x;
    int c = t * 4;
    float4 v = ((const float4*)(x + (size_t)row * DDQ))[t];
    float pe[4];
    #pragma unroll
    for (int i = 0; i < 4; i++) {
        int ci = c + i;
        float inv = exp2f(-((float)(2 * ci) * (1.0f / 512.0f)) * 13.2877123795494f);
        float ang = (float)s * inv;
        pe[i] = (ci & 1) ? cosf(ang) : sinf(ang);
    }
    v.x += pe[0]; v.y += pe[1]; v.z += pe[2]; v.w += pe[3];
    ((float4*)(g_res + (size_t)row * DDQ))[t] = v;

    float sm = v.x + v.y + v.z + v.w;
    float mean = blockReduceSum128(sm) * (1.0f / DDQ);
    float dx = v.x - mean, dy = v.y - mean, dz = v.z - mean, dw = v.w - mean;
    float s2 = dx*dx + dy*dy + dz*dz + dw*dw;
    float var = blockReduceSum128(s2) * (1.0f / DDQ);
    float inv = rsqrtf(var + 1e-5f);
    float ox = dx * inv * gm[c+0] + bt[c+0];
    float oy = dy * inv * gm[c+1] + bt[c+1];
    float oz = dz * inv * gm[c+2] + bt[c+2];
    float ow = dw * inv * gm[c+3] + bt[c+3];
    __half2* hp = (__half2*)(tgt + (size_t)row * DDQ + c);
    hp[0] = __floats2half2_rn(ox, oy);
    hp[1] = __floats2half2_rn(oz, ow);
}

// layernorm fp32 in -> fp16 out
__global__ void k_ln16(const float* __restrict__ in, __half* __restrict__ tgt,
                       const float* __restrict__ gm, const float* __restrict__ bt) {
    int row = blockIdx.x;
    int t = threadIdx.x;
    float4 v = ((const float4*)(in + (size_t)row * DDQ))[t];
    float s = v.x + v.y + v.z + v.w;
    float mean = blockReduceSum128(s) * (1.0f / DDQ);
    float dx = v.x - mean, dy = v.y - mean, dz = v.z - mean, dw = v.w - mean;
    float s2 = dx*dx + dy*dy + dz*dz + dw*dw;
    float var = blockReduceSum128(s2) * (1.0f / DDQ);
    float inv = rsqrtf(var + 1e-5f);
    int c = t * 4;
    float ox = dx * inv * gm[c+0] + bt[c+0];
    float oy = dy * inv * gm[c+1] + bt[c+1];
    float oz = dz * inv * gm[c+2] + bt[c+2];
    float ow = dw * inv * gm[c+3] + bt[c+3];
    __half2* hp = (__half2*)(tgt + (size_t)row * DDQ + c);
    hp[0] = __floats2half2_rn(ox, oy);
    hp[1] = __floats2half2_rn(oz, ow);
}

// depthwise conv (K=7, same padding), fp16 in/out.
// thread = 4 channels x 4 consecutive s positions (10 row-loads / 16 outputs).
__global__ void __launch_bounds__(256)
k_dwconv_h(const __half* __restrict__ in, const float* __restrict__ dw) {
    int idx = blockIdx.x * 256 + threadIdx.x;
    if (idx >= (MMQ / 4) * 128) return;
    int c4 = (idx & 127) * 4;
    int bs4 = idx >> 7;                 // 0..1535
    const int SC = SSQ / 4;             // 96
    int b = bs4 / SC, s0 = (bs4 - b * SC) * 4;

    float w[4][KKQ];
    #pragma unroll
    for (int i = 0; i < 4; i++)
        #pragma unroll
        for (int k = 0; k < KKQ; k++)
            w[i][k] = dw[(c4 + i) * KKQ + k];

    float acc[4][4] = {};
    #pragma unroll
    for (int r = 0; r < 10; r++) {
        int ss = s0 - 3 + r;
        if (ss >= 0 && ss < SSQ) {
            uint2 raw = *(const uint2*)&in[(((size_t)b * SSQ + ss) << 9) + c4];
            __half2 h01 = *reinterpret_cast<__half2*>(&raw.x);
            __half2 h23 = *reinterpret_cast<__half2*>(&raw.y);
            float2 f01 = __half22float2(h01), f23 = __half22float2(h23);
            #pragma unroll
            for (int j = 0; j < 4; j++) {
                int t = r - j;
                if (t >= 0 && t < KKQ) {
                    acc[j][0] += f01.x * w[0][t];
                    acc[j][1] += f01.y * w[1][t];
                    acc[j][2] += f23.x * w[2][t];
                    acc[j][3] += f23.y * w[3][t];
                }
            }
        }
    }
    #pragma unroll
    for (int j = 0; j < 4; j++) {
        __half2 o01 = __floats2half2_rn(acc[j][0], acc[j][1]);
        __half2 o23 = __floats2half2_rn(acc[j][2], acc[j][3]);
        uint2 o;
        o.x = *reinterpret_cast<uint32_t*>(&o01);
        o.y = *reinterpret_cast<uint32_t*>(&o23);
        *(uint2*)&g_xh[(((size_t)b * SSQ + s0 + j) << 9) + c4] = o;
    }
}

// single fused fp32->fp16 weight conversion for all 9 matrices (float4)
__global__ void k_f2h_all(const float* __restrict__ pw_w, const float* __restrict__ wq,
                          const float* __restrict__ wk, const float* __restrict__ wv,
                          const float* __restrict__ wo, const float* __restrict__ fw) {
    const int WSZ4 = (DDQ * DDQ) / 4;   // 65536 4-packs per matrix
    int idx4 = blockIdx.x * 256 + threadIdx.x;
    if (idx4 >= 9 * WSZ4) return;
    int seg = idx4 / WSZ4;
    int off4 = idx4 - seg * WSZ4;
    const float* src;
    if (seg < 4)      src = pw_w + (size_t)seg * DDQ * DDQ;
    else if (seg == 4) src = wq;
    else if (seg == 5) src = wk;
    else if (seg == 6) src = wv;
    else if (seg == 7) src = wo;
    else               src = fw;
    float4 v = ((const float4*)src)[off4];
    __half2 h01 = __floats2half2_rn(v.x, v.y), h23 = __floats2half2_rn(v.z, v.w);
    uint2 o;
    o.x = *reinterpret_cast<uint32_t*>(&h01);
    o.y = *reinterpret_cast<uint32_t*>(&h23);
    *(uint2*)&g_wh[((size_t)seg * DDQ * DDQ) + off4 * 4] = o;
}

// ---------------- host orchestration -----------------------------------------
extern "C" void kernel_launch(void* const* d_in, const int* in_sizes, int n_in,
                              void* d_out, int out_size) {
    const float* x    = (const float*)d_in[0];
    const int*   mask = (const int*)  d_in[1];
    const float* dw_w = (const float*)d_in[2];
    const float* pw_w = (const float*)d_in[3];
    const float* pw_b = (const float*)d_in[4];
    const float* cg   = (const float*)d_in[5];
    const float* cb   = (const float*)d_in[6];
    const float* pg   = (const float*)d_in[7];
    const float* pb   = (const float*)d_in[8];
    const float* wq   = (const float*)d_in[9];
    const float* bq   = (const float*)d_in[10];
    const float* wk   = (const float*)d_in[11];
    const float* bk   = (const float*)d_in[12];
    const float* wv   = (const float*)d_in[13];
    const float* bv   = (const float*)d_in[14];
    const float* wo   = (const float*)d_in[15];
    const float* bo   = (const float*)d_in[16];
    const float* fg   = (const float*)d_in[17];
    const float* fb   = (const float*)d_in[18];
    const float* fw   = (const float*)d_in[19];
    const float* fbi  = (const float*)d_in[20];
    float* out = (float*)d_out;

    float* p_res;
    __half *p_xh, *p_wh, *p_qh, *p_qkv;
    cudaGetSymbolAddress((void**)&p_res, g_res);
    cudaGetSymbolAddress((void**)&p_xh,  g_xh);
    cudaGetSymbolAddress((void**)&p_wh,  g_wh);
    cudaGetSymbolAddress((void**)&p_qh,  g_qh);
    cudaGetSymbolAddress((void**)&p_qkv, g_qkv);

    const int WSZ = DDQ * DDQ;  // 262144
    dim3 dg(8, 48);             // N=512: N/64, M/128
    dim3 dg3(24, 48);           // N=1536 fused QKV

    // 0. weights -> fp16 (one fused launch)
    k_f2h_all<<<(9 * WSZ / 4 + 255) / 256, 256>>>(pw_w, wq, wk, wv, wo, fw);

    // 1. res = x + PE ; LN -> fp16 (conv input in g_qh), fused
    k_addpos_ln<<<MMQ, 128>>>(x, p_qh, pg, pb);

    // 2. conv stack
    for (int l = 0; l < LLQ; l++) {
        k_dwconv_h<<<(MMQ / 4) * 128 / 256, 256>>>(p_qh, dw_w + l * DDQ * KKQ);
        k_gemm_h<1, 1, 0><<<dg, 256>>>(p_xh, p_wh + (size_t)l * WSZ,
                                       pw_b + l * DDQ, nullptr, nullptr,
                                       p_res, p_res, nullptr);
        k_ln16<<<MMQ, 128>>>(p_res, (l < LLQ - 1) ? p_qh : p_xh,
                             cg + l * DDQ, cb + l * DDQ);
    }

    // 3. attention: fused QKV projection -> flash -> output projection
    k_gemm_h<0, 0, 1><<<dg3, 256>>>(p_xh, p_wh + 4 * (size_t)WSZ,
                                    bq, bk, bv, nullptr, nullptr, p_qkv);
    k_flash<<<dim3(3, BHQ), 256>>>(mask);
    k_gemm_h<0, 1, 0><<<dg, 256>>>(p_xh, p_wh + 7 * (size_t)WSZ,
                                   bo, nullptr, nullptr, p_res, p_res, nullptr);

    // 4. feedforward: out = relu(LN(res) @ fw^T + fb) + res
    k_ln16<<<MMQ, 128>>>(p_res, p_xh, fg, fb);
    k_gemm_h<1, 1, 0><<<dg, 256>>>(p_xh, p_wh + 8 * (size_t)WSZ,
                                   fbi, nullptr, nullptr, p_res, out, nullptr);
}

// round 8
// speedup vs baseline: 7.9620x; 1.1960x over previous
#include <cuda_runtime.h>
#include <cuda_fp16.h>
#include <math.h>
#include <stdint.h>

// Problem constants
#define BB   16
#define SSQ  384
#define DDQ  512
#define HHQ  8
#define HDQ  64
#define LLQ  4
#define KKQ  7
#define MMQ  (BB*SSQ)      // 6144 rows
#define BHQ  (BB*HHQ)      // 128 batch*heads

// ---------------- scratch (device globals; no allocation allowed) -----------
__device__ float g_res[MMQ*DDQ];                        // fp32 residual spine
__device__ __half g_xh[MMQ*DDQ];                        // fp16 GEMM A operand
__device__ __half g_wh[9*DDQ*DDQ];                      // fp16 weights
__device__ __half g_qh[MMQ*DDQ];                        // LN16 out (conv input)
__device__ __half g_qkv[3*MMQ*DDQ];                     // fused QKV, head-major

// ================= low-level helpers =========================================
__device__ __forceinline__ uint32_t smem_u32(const void* p) {
    uint32_t a;
    asm("{ .reg .u64 t; cvta.to.shared.u64 t, %1; cvt.u32.u64 %0, t; }" : "=r"(a) : "l"(p));
    return a;
}
__device__ __forceinline__ void cpa16(uint32_t dst, const void* src) {
    asm volatile("cp.async.cg.shared.global [%0], [%1], 16;" :: "r"(dst), "l"(src) : "memory");
}
#define CP_COMMIT() asm volatile("cp.async.commit_group;" ::: "memory")
#define CP_WAIT(n)  asm volatile("cp.async.wait_group %0;" :: "n"(n) : "memory")

__device__ __forceinline__ void ldsm4(uint32_t* r, uint32_t addr) {
    asm volatile("ldmatrix.sync.aligned.m8n8.x4.shared.b16 {%0,%1,%2,%3}, [%4];"
                 : "=r"(r[0]), "=r"(r[1]), "=r"(r[2]), "=r"(r[3]) : "r"(addr));
}
__device__ __forceinline__ void ldsm4t(uint32_t* r, uint32_t addr) {
    asm volatile("ldmatrix.sync.aligned.m8n8.x4.trans.shared.b16 {%0,%1,%2,%3}, [%4];"
                 : "=r"(r[0]), "=r"(r[1]), "=r"(r[2]), "=r"(r[3]) : "r"(addr));
}
__device__ __forceinline__ void hmma(float* d, const uint32_t* a, uint32_t b0, uint32_t b1) {
    asm volatile(
        "mma.sync.aligned.m16n8k16.row.col.f32.f16.f16.f32 "
        "{%0,%1,%2,%3}, {%4,%5,%6,%7}, {%8,%9}, {%0,%1,%2,%3};"
        : "+f"(d[0]), "+f"(d[1]), "+f"(d[2]), "+f"(d[3])
        : "r"(a[0]), "r"(a[1]), "r"(a[2]), "r"(a[3]), "r"(b0), "r"(b1));
}
__device__ __forceinline__ uint32_t packh2(float x, float y) {
    __half2 h = __floats2half2_rn(x, y);
    return *reinterpret_cast<uint32_t*>(&h);
}

// ================= dense GEMM: Y[6144,N] = X@W^T + epilogue ==================
// X fp16 [M,512], W fp16 [N,512]. BM=128 BN=128 BK=64, 256 threads
// (8 warps, 4m x 2n, warp tile 32x64), cp.async 3-stage, 1 sync/iter (8 iters).
// SCATTER=1: fused QKV (N=1536), bias selected by n0>>9, out -> g_qkv head-major.
template<int RELU, int ADDRES, int SCATTER>
__global__ void __launch_bounds__(256, 2)
k_gemm_h(const __half* __restrict__ X, const __half* __restrict__ W,
         const float* __restrict__ bias, const float* __restrict__ bias2,
         const float* __restrict__ bias3, const float* __restrict__ res,
         float* __restrict__ outf, __half* __restrict__ outh) {
    __shared__ __half As[3][128 * 64];
    __shared__ __half Bs[3][128 * 64];
    const int tid = threadIdx.x, lane = tid & 31, wid = tid >> 5;
    const int wm = wid >> 1, wn = wid & 1;
    const int m0 = blockIdx.y * 128, n0 = blockIdx.x * 128;
    float acc[2][8][4] = {};

    const uint32_t aB[3] = { smem_u32(&As[0][0]), smem_u32(&As[1][0]), smem_u32(&As[2][0]) };
    const uint32_t bB[3] = { smem_u32(&Bs[0][0]), smem_u32(&Bs[1][0]), smem_u32(&Bs[2][0]) };

    auto load_stage = [&](int kt, int st) {
        // A: 128 rows x 64 halfs (8 sectors of 16B) = 1024 chunks, 4/thread
        #pragma unroll
        for (int i = 0; i < 4; i++) {
            int q = tid + i * 256; int r = q >> 3, c = q & 7;
            cpa16(aB[st] + r * 128 + ((c ^ (r & 7)) * 16),
                  X + (size_t)(m0 + r) * DDQ + kt * 64 + c * 8);
        }
        #pragma unroll
        for (int i = 0; i < 4; i++) {
            int q = tid + i * 256; int r = q >> 3, c = q & 7;
            cpa16(bB[st] + r * 128 + ((c ^ (r & 7)) * 16),
                  W + (size_t)(n0 + r) * DDQ + kt * 64 + c * 8);
        }
        CP_COMMIT();
    };

    load_stage(0, 0);
    load_stage(1, 1);

    #pragma unroll 1
    for (int kt = 0; kt < 8; kt++) {
        int st = kt % 3;
        if (kt < 7) { CP_WAIT(1); } else { CP_WAIT(0); }
        __syncthreads();
        if (kt + 2 < 8) load_stage(kt + 2, (kt + 2) % 3);

        #pragma unroll
        for (int ks = 0; ks < 4; ks++) {
            uint32_t a[2][4], bfr[4][4];
            #pragma unroll
            for (int mt = 0; mt < 2; mt++) {
                int r = wm * 32 + mt * 16 + (lane & 15);
                int c = ks * 2 + (lane >> 4);
                ldsm4(a[mt], aB[st] + r * 128 + ((c ^ (r & 7)) * 16));
            }
            #pragma unroll
            for (int np = 0; np < 4; np++) {
                int nr = wn * 64 + np * 16 + (lane & 7) + ((lane >> 4) << 3);
                int c = ks * 2 + ((lane >> 3) & 1);
                ldsm4(bfr[np], bB[st] + nr * 128 + ((c ^ (nr & 7)) * 16));
            }
            #pragma unroll
            for (int mt = 0; mt < 2; mt++)
                #pragma unroll
                for (int nt = 0; nt < 8; nt++)
                    hmma(acc[mt][nt], a[mt],
                         bfr[nt >> 1][(nt & 1) * 2], bfr[nt >> 1][(nt & 1) * 2 + 1]);
        }
    }

    // epilogue
    const int mat = n0 >> 9;          // QKV: which matrix this block serves
    const int col0 = n0 & 511;
    const float* bp = SCATTER ? ((mat == 0) ? bias : ((mat == 1) ? bias2 : bias3)) : bias;
    __half* ob = SCATTER ? (outh + (size_t)mat * MMQ * DDQ) : outh;
    #pragma unroll
    for (int mt = 0; mt < 2; mt++) {
        int r = m0 + wm * 32 + mt * 16 + (lane >> 2);
        #pragma unroll
        for (int nt = 0; nt < 8; nt++) {
            int cl = wn * 64 + nt * 8 + (lane & 3) * 2;
            int col = SCATTER ? (col0 + cl) : 0;
            int n = n0 + cl;
            float b0, b1;
            if (SCATTER) { b0 = bp[col]; b1 = bp[col + 1]; }
            else         { b0 = bp[n];   b1 = bp[n + 1]; }
            float v00 = acc[mt][nt][0] + b0, v01 = acc[mt][nt][1] + b1;
            float v10 = acc[mt][nt][2] + b0, v11 = acc[mt][nt][3] + b1;
            if (RELU) {
                v00 = fmaxf(v00, 0.f); v01 = fmaxf(v01, 0.f);
                v10 = fmaxf(v10, 0.f); v11 = fmaxf(v11, 0.f);
            }
            if (ADDRES) {
                float2 r0 = *(const float2*)&res[(size_t)r * DDQ + n];
                float2 r1 = *(const float2*)&res[(size_t)(r + 8) * DDQ + n];
                v00 += r0.x; v01 += r0.y; v10 += r1.x; v11 += r1.y;
            }
            if (SCATTER) {
                int h = col >> 6, hd = col & 63;
                int b_ = r / SSQ, s = r % SSQ;
                *(__half2*)&ob[(((size_t)(b_ * HHQ + h) * SSQ + s) << 6) + hd] =
                    __floats2half2_rn(v00, v01);
                int b2 = (r + 8) / SSQ, s2 = (r + 8) % SSQ;
                *(__half2*)&ob[(((size_t)(b2 * HHQ + h) * SSQ + s2) << 6) + hd] =
                    __floats2half2_rn(v10, v11);
            } else {
                *(float2*)&outf[(size_t)r * DDQ + n] = make_float2(v00, v01);
                *(float2*)&outf[(size_t)(r + 8) * DDQ + n] = make_float2(v10, v11);
            }
        }
    }
}

// ================= flash attention ==========================================
// One block = (q-tile of 128 rows) x (one bh). 8 warps, warp = 16 q-rows x all cols.
__global__ void __launch_bounds__(256)
k_flash(const int* __restrict__ mask) {
    __shared__ __half Qs[128 * 64];
    __shared__ __half Ks[128 * 64];
    __shared__ __half Vs[128 * 64];
    __shared__ int misk[128];
    const int bh = blockIdx.y, b = bh >> 3, h = bh & 7;
    const __half* Q = g_qkv + (size_t)bh * SSQ * HDQ;
    const __half* K = g_qkv + (size_t)MMQ * DDQ + (size_t)bh * SSQ * HDQ;
    const __half* V = g_qkv + 2 * (size_t)MMQ * DDQ + (size_t)bh * SSQ * HDQ;
    const int m0 = blockIdx.x * 128;
    const int tid = threadIdx.x, lane = tid & 31, w = tid >> 5;
    const uint32_t qB = smem_u32(Qs), kB = smem_u32(Ks), vB = smem_u32(Vs);

    #pragma unroll
    for (int i = 0; i < 4; i++) {
        int q = tid + i * 256; int r = q >> 3, c = q & 7;
        cpa16(qB + r * 128 + ((c ^ (r & 7)) * 16), Q + (size_t)(m0 + r) * HDQ + c * 8);
    }

    float o[8][4] = {};
    float mrow0 = -3.0e38f, mrow1 = -3.0e38f, lrow0 = 0.f, lrow1 = 0.f;
    const float LOG2E = 1.4426950408889634f;

    #pragma unroll 1
    for (int kc = 0; kc < 3; kc++) {
        if (tid < 128) misk[tid] = mask[b * SSQ + kc * 128 + tid];
        #pragma unroll
        for (int i = 0; i < 4; i++) {
            int q = tid + i * 256; int r = q >> 3, c = q & 7;
            cpa16(kB + r * 128 + ((c ^ (r & 7)) * 16),
                  K + (size_t)(kc * 128 + r) * HDQ + c * 8);
            cpa16(vB + r * 128 + ((c ^ (r & 7)) * 16),
                  V + (size_t)(kc * 128 + r) * HDQ + c * 8);
        }
        CP_COMMIT(); CP_WAIT(0);
        __syncthreads();

        float s[16][4] = {};
        #pragma unroll
        for (int ks = 0; ks < 4; ks++) {
            uint32_t a[4];
            { int r = w * 16 + (lane & 15);
              int c = ks * 2 + (lane >> 4);
              ldsm4(a, qB + r * 128 + ((c ^ (r & 7)) * 16)); }
            #pragma unroll
            for (int np = 0; np < 8; np++) {
                uint32_t bf[4];
                int nr = np * 16 + (lane & 7) + ((lane >> 4) << 3);
                int c = ks * 2 + ((lane >> 3) & 1);
                ldsm4(bf, kB + nr * 128 + ((c ^ (nr & 7)) * 16));
                hmma(s[np * 2 + 0], a, bf[0], bf[1]);
                hmma(s[np * 2 + 1], a, bf[2], bf[3]);
            }
        }

        float mx0 = -3.0e38f, mx1 = -3.0e38f;
        #pragma unroll
        for (int nt = 0; nt < 16; nt++) {
            int nc = nt * 8 + (lane & 3) * 2;
            int f0 = misk[nc], f1 = misk[nc + 1];
            s[nt][0] = f0 ? -1e10f : s[nt][0] * 0.125f;
            s[nt][1] = f1 ? -1e10f : s[nt][1] * 0.125f;
            s[nt][2] = f0 ? -1e10f : s[nt][2] * 0.125f;
            s[nt][3] = f1 ? -1e10f : s[nt][3] * 0.125f;
            mx0 = fmaxf(mx0, fmaxf(s[nt][0], s[nt][1]));
            mx1 = fmaxf(mx1, fmaxf(s[nt][2], s[nt][3]));
        }
        #pragma unroll
        for (int of = 1; of <= 2; of <<= 1) {
            mx0 = fmaxf(mx0, __shfl_xor_sync(0xffffffffu, mx0, of));
            mx1 = fmaxf(mx1, __shfl_xor_sync(0xffffffffu, mx1, of));
        }
        float mn0 = fmaxf(mrow0, mx0), mn1 = fmaxf(mrow1, mx1);
        float al0 = exp2f((mrow0 - mn0) * LOG2E);
        float al1 = exp2f((mrow1 - mn1) * LOG2E);
        mrow0 = mn0; mrow1 = mn1;

        float sum0 = 0.f, sum1 = 0.f;
        #pragma unroll
        for (int nt = 0; nt < 16; nt++) {
            s[nt][0] = exp2f((s[nt][0] - mn0) * LOG2E);
            s[nt][1] = exp2f((s[nt][1] - mn0) * LOG2E);
            s[nt][2] = exp2f((s[nt][2] - mn1) * LOG2E);
            s[nt][3] = exp2f((s[nt][3] - mn1) * LOG2E);
            sum0 += s[nt][0] + s[nt][1];
            sum1 += s[nt][2] + s[nt][3];
        }
        #pragma unroll
        for (int of = 1; of <= 2; of <<= 1) {
            sum0 += __shfl_xor_sync(0xffffffffu, sum0, of);
            sum1 += __shfl_xor_sync(0xffffffffu, sum1, of);
        }
        lrow0 = lrow0 * al0 + sum0;
        lrow1 = lrow1 * al1 + sum1;

        #pragma unroll
        for (int t = 0; t < 8; t++) {
            o[t][0] *= al0; o[t][1] *= al0; o[t][2] *= al1; o[t][3] *= al1;
        }

        #pragma unroll
        for (int kg = 0; kg < 8; kg++) {
            uint32_t a[4];
            a[0] = packh2(s[kg * 2][0],     s[kg * 2][1]);
            a[1] = packh2(s[kg * 2][2],     s[kg * 2][3]);
            a[2] = packh2(s[kg * 2 + 1][0], s[kg * 2 + 1][1]);
            a[3] = packh2(s[kg * 2 + 1][2], s[kg * 2 + 1][3]);
            #pragma unroll
            for (int vn = 0; vn < 4; vn++) {
                uint32_t bf[4];
                int row = kg * 16 + (lane & 7) + ((lane >> 3) & 1) * 8;
                int c = vn * 2 + (lane >> 4);
                ldsm4t(bf, vB + row * 128 + ((c ^ (row & 7)) * 16));
                hmma(o[vn * 2 + 0], a, bf[0], bf[1]);
                hmma(o[vn * 2 + 1], a, bf[2], bf[3]);
            }
        }
        __syncthreads();
    }

    float inv0 = 1.f / lrow0, inv1 = 1.f / lrow1;
    int m = m0 + w * 16 + (lane >> 2);
    #pragma unroll
    for (int t = 0; t < 8; t++) {
        int hd = t * 8 + (lane & 3) * 2;
        *(__half2*)&g_xh[((size_t)(b * SSQ + m)) * DDQ + h * HDQ + hd] =
            __floats2half2_rn(o[t][0] * inv0, o[t][1] * inv0);
        *(__half2*)&g_xh[((size_t)(b * SSQ + m + 8)) * DDQ + h * HDQ + hd] =
            __floats2half2_rn(o[t][2] * inv1, o[t][3] * inv1);
    }
}

// ================= elementwise / reduction kernels ===========================
__inline__ __device__ float blockReduceSum128(float val) {
    __shared__ float sh[4];
    int lane = threadIdx.x & 31, w = threadIdx.x >> 5;
    #pragma unroll
    for (int o = 16; o; o >>= 1) val += __shfl_xor_sync(0xffffffffu, val, o);
    if (lane == 0) sh[w] = val;
    __syncthreads();
    float r = sh[0] + sh[1] + sh[2] + sh[3];
    __syncthreads();
    return r;
}

// fused: res = x + PE; tgt(fp16) = LN(res)*g + b.  one block (128 thr) per row.
__global__ void k_addpos_ln(const float* __restrict__ x, __half* __restrict__ tgt,
                            const float* __restrict__ gm, const float* __restrict__ bt) {
    int row = blockIdx.x;
    int s = row % SSQ;
    int t = threadIdx.x;
    int c = t * 4;
    float4 v = ((const float4*)(x + (size_t)row * DDQ))[t];
    float pe[4];
    #pragma unroll
    for (int i = 0; i < 4; i++) {
        int ci = c + i;
        float inv = exp2f(-((float)(2 * ci) * (1.0f / 512.0f)) * 13.2877123795494f);
        float ang = (float)s * inv;
        pe[i] = (ci & 1) ? cosf(ang) : sinf(ang);
    }
    v.x += pe[0]; v.y += pe[1]; v.z += pe[2]; v.w += pe[3];
    ((float4*)(g_res + (size_t)row * DDQ))[t] = v;

    float sm = v.x + v.y + v.z + v.w;
    float mean = blockReduceSum128(sm) * (1.0f / DDQ);
    float dx = v.x - mean, dy = v.y - mean, dz = v.z - mean, dw = v.w - mean;
    float s2 = dx*dx + dy*dy + dz*dz + dw*dw;
    float var = blockReduceSum128(s2) * (1.0f / DDQ);
    float inv = rsqrtf(var + 1e-5f);
    float ox = dx * inv * gm[c+0] + bt[c+0];
    float oy = dy * inv * gm[c+1] + bt[c+1];
    float oz = dz * inv * gm[c+2] + bt[c+2];
    float ow = dw * inv * gm[c+3] + bt[c+3];
    __half2* hp = (__half2*)(tgt + (size_t)row * DDQ + c);
    hp[0] = __floats2half2_rn(ox, oy);
    hp[1] = __floats2half2_rn(oz, ow);
}

// layernorm fp32 in -> fp16 out
__global__ void k_ln16(const float* __restrict__ in, __half* __restrict__ tgt,
                       const float* __restrict__ gm, const float* __restrict__ bt) {
    int row = blockIdx.x;
    int t = threadIdx.x;
    float4 v = ((const float4*)(in + (size_t)row * DDQ))[t];
    float s = v.x + v.y + v.z + v.w;
    float mean = blockReduceSum128(s) * (1.0f / DDQ);
    float dx = v.x - mean, dy = v.y - mean, dz = v.z - mean, dw = v.w - mean;
    float s2 = dx*dx + dy*dy + dz*dz + dw*dw;
    float var = blockReduceSum128(s2) * (1.0f / DDQ);
    float inv = rsqrtf(var + 1e-5f);
    int c = t * 4;
    float ox = dx * inv * gm[c+0] + bt[c+0];
    float oy = dy * inv * gm[c+1] + bt[c+1];
    float oz = dz * inv * gm[c+2] + bt[c+2];
    float ow = dw * inv * gm[c+3] + bt[c+3];
    __half2* hp = (__half2*)(tgt + (size_t)row * DDQ + c);
    hp[0] = __floats2half2_rn(ox, oy);
    hp[1] = __floats2half2_rn(oz, ow);
}

// depthwise conv (K=7, same padding), fp16 in/out.
// thread = 4 channels x 4 consecutive s positions (10 row-loads / 16 outputs).
__global__ void __launch_bounds__(256)
k_dwconv_h(const __half* __restrict__ in, const float* __restrict__ dw) {
    int idx = blockIdx.x * 256 + threadIdx.x;
    if (idx >= (MMQ / 4) * 128) return;
    int c4 = (idx & 127) * 4;
    int bs4 = idx >> 7;                 // 0..1535
    const int SC = SSQ / 4;             // 96
    int b = bs4 / SC, s0 = (bs4 - b * SC) * 4;

    float w[4][KKQ];
    #pragma unroll
    for (int i = 0; i < 4; i++)
        #pragma unroll
        for (int k = 0; k < KKQ; k++)
            w[i][k] = dw[(c4 + i) * KKQ + k];

    float acc[4][4] = {};
    #pragma unroll
    for (int r = 0; r < 10; r++) {
        int ss = s0 - 3 + r;
        if (ss >= 0 && ss < SSQ) {
            uint2 raw = *(const uint2*)&in[(((size_t)b * SSQ + ss) << 9) + c4];
            __half2 h01 = *reinterpret_cast<__half2*>(&raw.x);
            __half2 h23 = *reinterpret_cast<__half2*>(&raw.y);
            float2 f01 = __half22float2(h01), f23 = __half22float2(h23);
            #pragma unroll
            for (int j = 0; j < 4; j++) {
                int t = r - j;
                if (t >= 0 && t < KKQ) {
                    acc[j][0] += f01.x * w[0][t];
                    acc[j][1] += f01.y * w[1][t];
                    acc[j][2] += f23.x * w[2][t];
                    acc[j][3] += f23.y * w[3][t];
                }
            }
        }
    }
    #pragma unroll
    for (int j = 0; j < 4; j++) {
        __half2 o01 = __floats2half2_rn(acc[j][0], acc[j][1]);
        __half2 o23 = __floats2half2_rn(acc[j][2], acc[j][3]);
        uint2 o;
        o.x = *reinterpret_cast<uint32_t*>(&o01);
        o.y = *reinterpret_cast<uint32_t*>(&o23);
        *(uint2*)&g_xh[(((size_t)b * SSQ + s0 + j) << 9) + c4] = o;
    }
}

// single fused fp32->fp16 weight conversion for all 9 matrices (float4)
__global__ void k_f2h_all(const float* __restrict__ pw_w, const float* __restrict__ wq,
                          const float* __restrict__ wk, const float* __restrict__ wv,
                          const float* __restrict__ wo, const float* __restrict__ fw) {
    const int WSZ4 = (DDQ * DDQ) / 4;   // 65536 4-packs per matrix
    int idx4 = blockIdx.x * 256 + threadIdx.x;
    if (idx4 >= 9 * WSZ4) return;
    int seg = idx4 / WSZ4;
    int off4 = idx4 - seg * WSZ4;
    const float* src;
    if (seg < 4)      src = pw_w + (size_t)seg * DDQ * DDQ;
    else if (seg == 4) src = wq;
    else if (seg == 5) src = wk;
    else if (seg == 6) src = wv;
    else if (seg == 7) src = wo;
    else               src = fw;
    float4 v = ((const float4*)src)[off4];
    __half2 h01 = __floats2half2_rn(v.x, v.y), h23 = __floats2half2_rn(v.z, v.w);
    uint2 o;
    o.x = *reinterpret_cast<uint32_t*>(&h01);
    o.y = *reinterpret_cast<uint32_t*>(&h23);
    *(uint2*)&g_wh[((size_t)seg * DDQ * DDQ) + off4 * 4] = o;
}

// ---------------- host orchestration -----------------------------------------
extern "C" void kernel_launch(void* const* d_in, const int* in_sizes, int n_in,
                              void* d_out, int out_size) {
    const float* x    = (const float*)d_in[0];
    const int*   mask = (const int*)  d_in[1];
    const float* dw_w = (const float*)d_in[2];
    const float* pw_w = (const float*)d_in[3];
    const float* pw_b = (const float*)d_in[4];
    const float* cg   = (const float*)d_in[5];
    const float* cb   = (const float*)d_in[6];
    const float* pg   = (const float*)d_in[7];
    const float* pb   = (const float*)d_in[8];
    const float* wq   = (const float*)d_in[9];
    const float* bq   = (const float*)d_in[10];
    const float* wk   = (const float*)d_in[11];
    const float* bk   = (const float*)d_in[12];
    const float* wv   = (const float*)d_in[13];
    const float* bv   = (const float*)d_in[14];
    const float* wo   = (const float*)d_in[15];
    const float* bo   = (const float*)d_in[16];
    const float* fg   = (const float*)d_in[17];
    const float* fb   = (const float*)d_in[18];
    const float* fw   = (const float*)d_in[19];
    const float* fbi  = (const float*)d_in[20];
    float* out = (float*)d_out;

    float* p_res;
    __half *p_xh, *p_wh, *p_qh, *p_qkv;
    cudaGetSymbolAddress((void**)&p_res, g_res);
    cudaGetSymbolAddress((void**)&p_xh,  g_xh);
    cudaGetSymbolAddress((void**)&p_wh,  g_wh);
    cudaGetSymbolAddress((void**)&p_qh,  g_qh);
    cudaGetSymbolAddress((void**)&p_qkv, g_qkv);

    const int WSZ = DDQ * DDQ;  // 262144
    dim3 dg(4, 48);             // N=512: N/128, M/128
    dim3 dg3(12, 48);           // N=1536 fused QKV

    // 0. weights -> fp16 (one fused launch)
    k_f2h_all<<<(9 * WSZ / 4 + 255) / 256, 256>>>(pw_w, wq, wk, wv, wo, fw);

    // 1. res = x + PE ; LN -> fp16 (conv input in g_qh), fused
    k_addpos_ln<<<MMQ, 128>>>(x, p_qh, pg, pb);

    // 2. conv stack
    for (int l = 0; l < LLQ; l++) {
        k_dwconv_h<<<(MMQ / 4) * 128 / 256, 256>>>(p_qh, dw_w + l * DDQ * KKQ);
        k_gemm_h<1, 1, 0><<<dg, 256>>>(p_xh, p_wh + (size_t)l * WSZ,
                                       pw_b + l * DDQ, nullptr, nullptr,
                                       p_res, p_res, nullptr);
        k_ln16<<<MMQ, 128>>>(p_res, (l < LLQ - 1) ? p_qh : p_xh,
                             cg + l * DDQ, cb + l * DDQ);
    }

    // 3. attention: fused QKV projection -> flash -> output projection
    k_gemm_h<0, 0, 1><<<dg3, 256>>>(p_xh, p_wh + 4 * (size_t)WSZ,
                                    bq, bk, bv, nullptr, nullptr, p_qkv);
    k_flash<<<dim3(3, BHQ), 256>>>(mask);
    k_gemm_h<0, 1, 0><<<dg, 256>>>(p_xh, p_wh + 7 * (size_t)WSZ,
                                   bo, nullptr, nullptr, p_res, p_res, nullptr);

    // 4. feedforward: out = relu(LN(res) @ fw^T + fb) + res
    k_ln16<<<MMQ, 128>>>(p_res, p_xh, fg, fb);
    k_gemm_h<1, 1, 0><<<dg, 256>>>(p_xh, p_wh + 8 * (size_t)WSZ,
                                   fbi, nullptr, nullptr, p_res, out, nullptr);
}

// round 9
// speedup vs baseline: 8.2145x; 1.0317x over previous
#include <cuda_runtime.h>
#include <cuda_fp16.h>
#include <math.h>
#include <stdint.h>

// Problem constants
#define BB   16
#define SSQ  384
#define DDQ  512
#define HHQ  8
#define HDQ  64
#define LLQ  4
#define KKQ  7
#define MMQ  (BB*SSQ)      // 6144 rows
#define BHQ  (BB*HHQ)      // 128 batch*heads

// ---------------- scratch (device globals; no allocation allowed) -----------
__device__ float g_res[MMQ*DDQ];                        // fp32 residual spine
__device__ __half g_xh[MMQ*DDQ];                        // fp16 GEMM A operand
__device__ __half g_yh[MMQ*DDQ];                        // fp16 GEMM Y output
__device__ __half g_wh[9*DDQ*DDQ];                      // fp16 weights
__device__ __half g_qh[MMQ*DDQ];                        // LN16 out (conv input)
__device__ __half g_qkv[3*MMQ*DDQ];                     // fused QKV, head-major

// ================= low-level helpers =========================================
__device__ __forceinline__ uint32_t smem_u32(const void* p) {
    uint32_t a;
    asm("{ .reg .u64 t; cvta.to.shared.u64 t, %1; cvt.u32.u64 %0, t; }" : "=r"(a) : "l"(p));
    return a;
}
__device__ __forceinline__ void cpa16(uint32_t dst, const void* src) {
    asm volatile("cp.async.cg.shared.global [%0], [%1], 16;" :: "r"(dst), "l"(src) : "memory");
}
#define CP_COMMIT() asm volatile("cp.async.commit_group;" ::: "memory")
#define CP_WAIT(n)  asm volatile("cp.async.wait_group %0;" :: "n"(n) : "memory")

__device__ __forceinline__ void ldsm4(uint32_t* r, uint32_t addr) {
    asm volatile("ldmatrix.sync.aligned.m8n8.x4.shared.b16 {%0,%1,%2,%3}, [%4];"
                 : "=r"(r[0]), "=r"(r[1]), "=r"(r[2]), "=r"(r[3]) : "r"(addr));
}
__device__ __forceinline__ void ldsm4t(uint32_t* r, uint32_t addr) {
    asm volatile("ldmatrix.sync.aligned.m8n8.x4.trans.shared.b16 {%0,%1,%2,%3}, [%4];"
                 : "=r"(r[0]), "=r"(r[1]), "=r"(r[2]), "=r"(r[3]) : "r"(addr));
}
__device__ __forceinline__ void hmma(float* d, const uint32_t* a, uint32_t b0, uint32_t b1) {
    asm volatile(
        "mma.sync.aligned.m16n8k16.row.col.f32.f16.f16.f32 "
        "{%0,%1,%2,%3}, {%4,%5,%6,%7}, {%8,%9}, {%0,%1,%2,%3};"
        : "+f"(d[0]), "+f"(d[1]), "+f"(d[2]), "+f"(d[3])
        : "r"(a[0]), "r"(a[1]), "r"(a[2]), "r"(a[3]), "r"(b0), "r"(b1));
}
__device__ __forceinline__ uint32_t packh2(float x, float y) {
    __half2 h = __floats2half2_rn(x, y);
    return *reinterpret_cast<uint32_t*>(&h);
}

// ================= dense GEMM: Y[6144,N] = X@W^T + epilogue ==================
// X fp16 [M,512], W fp16 [N,512]. BM=128 BN=128 BK=64, 256 threads
// (8 warps, 4m x 2n, warp tile 32x64), cp.async 3-stage, 1 sync/iter (8 iters).
// MODE 0: Y fp16 -> outh [M,512] (lean epilogue; res-add deferred to k_addln)
// MODE 1: fused QKV (N=1536), bias by n0>>9, scatter to g_qkv head-major
// MODE 2: fp32 out with +res (final FF layer)
template<int RELU, int MODE>
__global__ void __launch_bounds__(256, 2)
k_gemm_h(const __half* __restrict__ X, const __half* __restrict__ W,
         const float* __restrict__ bias, const float* __restrict__ bias2,
         const float* __restrict__ bias3, const float* __restrict__ res,
         float* __restrict__ outf, __half* __restrict__ outh) {
    __shared__ __half As[3][128 * 64];
    __shared__ __half Bs[3][128 * 64];
    const int tid = threadIdx.x, lane = tid & 31, wid = tid >> 5;
    const int wm = wid >> 1, wn = wid & 1;
    const int m0 = blockIdx.y * 128, n0 = blockIdx.x * 128;
    float acc[2][8][4] = {};

    const uint32_t aB[3] = { smem_u32(&As[0][0]), smem_u32(&As[1][0]), smem_u32(&As[2][0]) };
    const uint32_t bB[3] = { smem_u32(&Bs[0][0]), smem_u32(&Bs[1][0]), smem_u32(&Bs[2][0]) };

    auto load_stage = [&](int kt, int st) {
        #pragma unroll
        for (int i = 0; i < 4; i++) {
            int q = tid + i * 256; int r = q >> 3, c = q & 7;
            cpa16(aB[st] + r * 128 + ((c ^ (r & 7)) * 16),
                  X + (size_t)(m0 + r) * DDQ + kt * 64 + c * 8);
        }
        #pragma unroll
        for (int i = 0; i < 4; i++) {
            int q = tid + i * 256; int r = q >> 3, c = q & 7;
            cpa16(bB[st] + r * 128 + ((c ^ (r & 7)) * 16),
                  W + (size_t)(n0 + r) * DDQ + kt * 64 + c * 8);
        }
        CP_COMMIT();
    };

    load_stage(0, 0);
    load_stage(1, 1);

    #pragma unroll 1
    for (int kt = 0; kt < 8; kt++) {
        int st = kt % 3;
        if (kt < 7) { CP_WAIT(1); } else { CP_WAIT(0); }
        __syncthreads();
        if (kt + 2 < 8) load_stage(kt + 2, (kt + 2) % 3);

        #pragma unroll
        for (int ks = 0; ks < 4; ks++) {
            uint32_t a[2][4], bfr[4][4];
            #pragma unroll
            for (int mt = 0; mt < 2; mt++) {
                int r = wm * 32 + mt * 16 + (lane & 15);
                int c = ks * 2 + (lane >> 4);
                ldsm4(a[mt], aB[st] + r * 128 + ((c ^ (r & 7)) * 16));
            }
            #pragma unroll
            for (int np = 0; np < 4; np++) {
                int nr = wn * 64 + np * 16 + (lane & 7) + ((lane >> 4) << 3);
                int c = ks * 2 + ((lane >> 3) & 1);
                ldsm4(bfr[np], bB[st] + nr * 128 + ((c ^ (nr & 7)) * 16));
            }
            #pragma unroll
            for (int mt = 0; mt < 2; mt++)
                #pragma unroll
                for (int nt = 0; nt < 8; nt++)
                    hmma(acc[mt][nt], a[mt],
                         bfr[nt >> 1][(nt & 1) * 2], bfr[nt >> 1][(nt & 1) * 2 + 1]);
        }
    }

    // epilogue
    const int mat = n0 >> 9;
    const int col0 = n0 & 511;
    const float* bp = (MODE == 1) ? ((mat == 0) ? bias : ((mat == 1) ? bias2 : bias3)) : bias;
    __half* ob = (MODE == 1) ? (outh + (size_t)mat * MMQ * DDQ) : outh;
    #pragma unroll
    for (int mt = 0; mt < 2; mt++) {
        int r = m0 + wm * 32 + mt * 16 + (lane >> 2);
        #pragma unroll
        for (int nt = 0; nt < 8; nt++) {
            int cl = wn * 64 + nt * 8 + (lane & 3) * 2;
            int col = (MODE == 1) ? (col0 + cl) : 0;
            int n = n0 + cl;
            float b0, b1;
            if (MODE == 1) { b0 = bp[col]; b1 = bp[col + 1]; }
            else           { b0 = bp[n];   b1 = bp[n + 1]; }
            float v00 = acc[mt][nt][0] + b0, v01 = acc[mt][nt][1] + b1;
            float v10 = acc[mt][nt][2] + b0, v11 = acc[mt][nt][3] + b1;
            if (RELU) {
                v00 = fmaxf(v00, 0.f); v01 = fmaxf(v01, 0.f);
                v10 = fmaxf(v10, 0.f); v11 = fmaxf(v11, 0.f);
            }
            if (MODE == 0) {
                *(__half2*)&ob[(size_t)r * DDQ + n] = __floats2half2_rn(v00, v01);
                *(__half2*)&ob[(size_t)(r + 8) * DDQ + n] = __floats2half2_rn(v10, v11);
            } else if (MODE == 1) {
                int h = col >> 6, hd = col & 63;
                int b_ = r / SSQ, s = r % SSQ;
                *(__half2*)&ob[(((size_t)(b_ * HHQ + h) * SSQ + s) << 6) + hd] =
                    __floats2half2_rn(v00, v01);
                int b2 = (r + 8) / SSQ, s2 = (r + 8) % SSQ;
                *(__half2*)&ob[(((size_t)(b2 * HHQ + h) * SSQ + s2) << 6) + hd] =
                    __floats2half2_rn(v10, v11);
            } else {
                float2 r0 = *(const float2*)&res[(size_t)r * DDQ + n];
                float2 r1 = *(const float2*)&res[(size_t)(r + 8) * DDQ + n];
                *(float2*)&outf[(size_t)r * DDQ + n] = make_float2(v00 + r0.x, v01 + r0.y);
                *(float2*)&outf[(size_t)(r + 8) * DDQ + n] = make_float2(v10 + r1.x, v11 + r1.y);
            }
        }
    }
}

// ================= flash attention ==========================================
__global__ void __launch_bounds__(256)
k_flash(const int* __restrict__ mask) {
    __shared__ __half Qs[128 * 64];
    __shared__ __half Ks[128 * 64];
    __shared__ __half Vs[128 * 64];
    __shared__ int misk[128];
    const int bh = blockIdx.y, b = bh >> 3, h = bh & 7;
    const __half* Q = g_qkv + (size_t)bh * SSQ * HDQ;
    const __half* K = g_qkv + (size_t)MMQ * DDQ + (size_t)bh * SSQ * HDQ;
    const __half* V = g_qkv + 2 * (size_t)MMQ * DDQ + (size_t)bh * SSQ * HDQ;
    const int m0 = blockIdx.x * 128;
    const int tid = threadIdx.x, lane = tid & 31, w = tid >> 5;
    const uint32_t qB = smem_u32(Qs), kB = smem_u32(Ks), vB = smem_u32(Vs);

    #pragma unroll
    for (int i = 0; i < 4; i++) {
        int q = tid + i * 256; int r = q >> 3, c = q & 7;
        cpa16(qB + r * 128 + ((c ^ (r & 7)) * 16), Q + (size_t)(m0 + r) * HDQ + c * 8);
    }

    float o[8][4] = {};
    float mrow0 = -3.0e38f, mrow1 = -3.0e38f, lrow0 = 0.f, lrow1 = 0.f;
    const float LOG2E = 1.4426950408889634f;

    #pragma unroll 1
    for (int kc = 0; kc < 3; kc++) {
        if (tid < 128) misk[tid] = mask[b * SSQ + kc * 128 + tid];
        #pragma unroll
        for (int i = 0; i < 4; i++) {
            int q = tid + i * 256; int r = q >> 3, c = q & 7;
            cpa16(kB + r * 128 + ((c ^ (r & 7)) * 16),
                  K + (size_t)(kc * 128 + r) * HDQ + c * 8);
            cpa16(vB + r * 128 + ((c ^ (r & 7)) * 16),
                  V + (size_t)(kc * 128 + r) * HDQ + c * 8);
        }
        CP_COMMIT(); CP_WAIT(0);
        __syncthreads();

        float s[16][4] = {};
        #pragma unroll
        for (int ks = 0; ks < 4; ks++) {
            uint32_t a[4];
            { int r = w * 16 + (lane & 15);
              int c = ks * 2 + (lane >> 4);
              ldsm4(a, qB + r * 128 + ((c ^ (r & 7)) * 16)); }
            #pragma unroll
            for (int np = 0; np < 8; np++) {
                uint32_t bf[4];
                int nr = np * 16 + (lane & 7) + ((lane >> 4) << 3);
                int c = ks * 2 + ((lane >> 3) & 1);
                ldsm4(bf, kB + nr * 128 + ((c ^ (nr & 7)) * 16));
                hmma(s[np * 2 + 0], a, bf[0], bf[1]);
                hmma(s[np * 2 + 1], a, bf[2], bf[3]);
            }
        }

        float mx0 = -3.0e38f, mx1 = -3.0e38f;
        #pragma unroll
        for (int nt = 0; nt < 16; nt++) {
            int nc = nt * 8 + (lane & 3) * 2;
            int f0 = misk[nc], f1 = misk[nc + 1];
            s[nt][0] = f0 ? -1e10f : s[nt][0] * 0.125f;
            s[nt][1] = f1 ? -1e10f : s[nt][1] * 0.125f;
            s[nt][2] = f0 ? -1e10f : s[nt][2] * 0.125f;
            s[nt][3] = f1 ? -1e10f : s[nt][3] * 0.125f;
            mx0 = fmaxf(mx0, fmaxf(s[nt][0], s[nt][1]));
            mx1 = fmaxf(mx1, fmaxf(s[nt][2], s[nt][3]));
        }
        #pragma unroll
        for (int of = 1; of <= 2; of <<= 1) {
            mx0 = fmaxf(mx0, __shfl_xor_sync(0xffffffffu, mx0, of));
            mx1 = fmaxf(mx1, __shfl_xor_sync(0xffffffffu, mx1, of));
        }
        float mn0 = fmaxf(mrow0, mx0), mn1 = fmaxf(mrow1, mx1);
        float al0 = exp2f((mrow0 - mn0) * LOG2E);
        float al1 = exp2f((mrow1 - mn1) * LOG2E);
        mrow0 = mn0; mrow1 = mn1;

        float sum0 = 0.f, sum1 = 0.f;
        #pragma unroll
        for (int nt = 0; nt < 16; nt++) {
            s[nt][0] = exp2f((s[nt][0] - mn0) * LOG2E);
            s[nt][1] = exp2f((s[nt][1] - mn0) * LOG2E);
            s[nt][2] = exp2f((s[nt][2] - mn1) * LOG2E);
            s[nt][3] = exp2f((s[nt][3] - mn1) * LOG2E);
            sum0 += s[nt][0] + s[nt][1];
            sum1 += s[nt][2] + s[nt][3];
        }
        #pragma unroll
        for (int of = 1; of <= 2; of <<= 1) {
            sum0 += __shfl_xor_sync(0xffffffffu, sum0, of);
            sum1 += __shfl_xor_sync(0xffffffffu, sum1, of);
        }
        lrow0 = lrow0 * al0 + sum0;
        lrow1 = lrow1 * al1 + sum1;

        #pragma unroll
        for (int t = 0; t < 8; t++) {
            o[t][0] *= al0; o[t][1] *= al0; o[t][2] *= al1; o[t][3] *= al1;
        }

        #pragma unroll
        for (int kg = 0; kg < 8; kg++) {
            uint32_t a[4];
            a[0] = packh2(s[kg * 2][0],     s[kg * 2][1]);
            a[1] = packh2(s[kg * 2][2],     s[kg * 2][3]);
            a[2] = packh2(s[kg * 2 + 1][0], s[kg * 2 + 1][1]);
            a[3] = packh2(s[kg * 2 + 1][2], s[kg * 2 + 1][3]);
            #pragma unroll
            for (int vn = 0; vn < 4; vn++) {
                uint32_t bf[4];
                int row = kg * 16 + (lane & 7) + ((lane >> 3) & 1) * 8;
                int c = vn * 2 + (lane >> 4);
                ldsm4t(bf, vB + row * 128 + ((c ^ (row & 7)) * 16));
                hmma(o[vn * 2 + 0], a, bf[0], bf[1]);
                hmma(o[vn * 2 + 1], a, bf[2], bf[3]);
            }
        }
        __syncthreads();
    }

    float inv0 = 1.f / lrow0, inv1 = 1.f / lrow1;
    int m = m0 + w * 16 + (lane >> 2);
    #pragma unroll
    for (int t = 0; t < 8; t++) {
        int hd = t * 8 + (lane & 3) * 2;
        *(__half2*)&g_xh[((size_t)(b * SSQ + m)) * DDQ + h * HDQ + hd] =
            __floats2half2_rn(o[t][0] * inv0, o[t][1] * inv0);
        *(__half2*)&g_xh[((size_t)(b * SSQ + m + 8)) * DDQ + h * HDQ + hd] =
            __floats2half2_rn(o[t][2] * inv1, o[t][3] * inv1);
    }
}

// ================= elementwise / reduction kernels ===========================
__inline__ __device__ float blockReduceSum128(float val) {
    __shared__ float sh[4];
    int lane = threadIdx.x & 31, w = threadIdx.x >> 5;
    #pragma unroll
    for (int o = 16; o; o >>= 1) val += __shfl_xor_sync(0xffffffffu, val, o);
    if (lane == 0) sh[w] = val;
    __syncthreads();
    float r = sh[0] + sh[1] + sh[2] + sh[3];
    __syncthreads();
    return r;
}

// fused: res = x + PE; tgt(fp16) = LN(res)*g + b.  one block (128 thr) per row.
__global__ void k_addpos_ln(const float* __restrict__ x, __half* __restrict__ tgt,
                            const float* __restrict__ gm, const float* __restrict__ bt) {
    int row = blockIdx.x;
    int s = row % SSQ;
    int t = threadIdx.x;
    int c = t * 4;
    float4 v = ((const float4*)(x + (size_t)row * DDQ))[t];
    float pe[4];
    #pragma unroll
    for (int i = 0; i < 4; i++) {
        int ci = c + i;
        float inv = exp2f(-((float)(2 * ci) * (1.0f / 512.0f)) * 13.2877123795494f);
        float ang = (float)s * inv;
        pe[i] = (ci & 1) ? cosf(ang) : sinf(ang);
    }
    v.x += pe[0]; v.y += pe[1]; v.z += pe[2]; v.w += pe[3];
    ((float4*)(g_res + (size_t)row * DDQ))[t] = v;

    float sm = v.x + v.y + v.z + v.w;
    float mean = blockReduceSum128(sm) * (1.0f / DDQ);
    float dx = v.x - mean, dy = v.y - mean, dz = v.z - mean, dw = v.w - mean;
    float s2 = dx*dx + dy*dy + dz*dz + dw*dw;
    float var = blockReduceSum128(s2) * (1.0f / DDQ);
    float inv = rsqrtf(var + 1e-5f);
    float ox = dx * inv * gm[c+0] + bt[c+0];
    float oy = dy * inv * gm[c+1] + bt[c+1];
    float oz = dz * inv * gm[c+2] + bt[c+2];
    float ow = dw * inv * gm[c+3] + bt[c+3];
    __half2* hp = (__half2*)(tgt + (size_t)row * DDQ + c);
    hp[0] = __floats2half2_rn(ox, oy);
    hp[1] = __floats2half2_rn(oz, ow);
}

// fused: res += Y(fp16); tgt(fp16) = LN(res)*g + b.  one block (128 thr) per row.
__global__ void k_addln(const __half* __restrict__ y, __half* __restrict__ tgt,
                        const float* __restrict__ gm, const float* __restrict__ bt) {
    int row = blockIdx.x;
    int t = threadIdx.x;
    int c = t * 4;
    float4 v = ((const float4*)(g_res + (size_t)row * DDQ))[t];
    uint2 raw = *(const uint2*)&y[(size_t)row * DDQ + c];
    __half2 y01 = *reinterpret_cast<__half2*>(&raw.x);
    __half2 y23 = *reinterpret_cast<__half2*>(&raw.y);
    float2 f01 = __half22float2(y01), f23 = __half22float2(y23);
    v.x += f01.x; v.y += f01.y; v.z += f23.x; v.w += f23.y;
    ((float4*)(g_res + (size_t)row * DDQ))[t] = v;

    float sm = v.x + v.y + v.z + v.w;
    float mean = blockReduceSum128(sm) * (1.0f / DDQ);
    float dx = v.x - mean, dy = v.y - mean, dz = v.z - mean, dw = v.w - mean;
    float s2 = dx*dx + dy*dy + dz*dz + dw*dw;
    float var = blockReduceSum128(s2) * (1.0f / DDQ);
    float inv = rsqrtf(var + 1e-5f);
    float ox = dx * inv * gm[c+0] + bt[c+0];
    float oy = dy * inv * gm[c+1] + bt[c+1];
    float oz = dz * inv * gm[c+2] + bt[c+2];
    float ow = dw * inv * gm[c+3] + bt[c+3];
    __half2* hp = (__half2*)(tgt + (size_t)row * DDQ + c);
    hp[0] = __floats2half2_rn(ox, oy);
    hp[1] = __floats2half2_rn(oz, ow);
}

// depthwise conv (K=7, same padding), fp16 in/out.
__global__ void __launch_bounds__(256)
k_dwconv_h(const __half* __restrict__ in, const float* __restrict__ dw) {
    int idx = blockIdx.x * 256 + threadIdx.x;
    if (idx >= (MMQ / 4) * 128) return;
    int c4 = (idx & 127) * 4;
    int bs4 = idx >> 7;
    const int SC = SSQ / 4;
    int b = bs4 / SC, s0 = (bs4 - b * SC) * 4;

    float w[4][KKQ];
    #pragma unroll
    for (int i = 0; i < 4; i++)
        #pragma unroll
        for (int k = 0; k < KKQ; k++)
            w[i][k] = dw[(c4 + i) * KKQ + k];

    float acc[4][4] = {};
    #pragma unroll
    for (int r = 0; r < 10; r++) {
        int ss = s0 - 3 + r;
        if (ss >= 0 && ss < SSQ) {
            uint2 raw = *(const uint2*)&in[(((size_t)b * SSQ + ss) << 9) + c4];
            __half2 h01 = *reinterpret_cast<__half2*>(&raw.x);
            __half2 h23 = *reinterpret_cast<__half2*>(&raw.y);
            float2 f01 = __half22float2(h01), f23 = __half22float2(h23);
            #pragma unroll
            for (int j = 0; j < 4; j++) {
                int t = r - j;
                if (t >= 0 && t < KKQ) {
                    acc[j][0] += f01.x * w[0][t];
                    acc[j][1] += f01.y * w[1][t];
                    acc[j][2] += f23.x * w[2][t];
                    acc[j][3] += f23.y * w[3][t];
                }
            }
        }
    }
    #pragma unroll
    for (int j = 0; j < 4; j++) {
        __half2 o01 = __floats2half2_rn(acc[j][0], acc[j][1]);
        __half2 o23 = __floats2half2_rn(acc[j][2], acc[j][3]);
        uint2 o;
        o.x = *reinterpret_cast<uint32_t*>(&o01);
        o.y = *reinterpret_cast<uint32_t*>(&o23);
        *(uint2*)&g_xh[(((size_t)b * SSQ + s0 + j) << 9) + c4] = o;
    }
}

// single fused fp32->fp16 weight conversion for all 9 matrices (float4)
__global__ void k_f2h_all(const float* __restrict__ pw_w, const float* __restrict__ wq,
                          const float* __restrict__ wk, const float* __restrict__ wv,
                          const float* __restrict__ wo, const float* __restrict__ fw) {
    const int WSZ4 = (DDQ * DDQ) / 4;
    int idx4 = blockIdx.x * 256 + threadIdx.x;
    if (idx4 >= 9 * WSZ4) return;
    int seg = idx4 / WSZ4;
    int off4 = idx4 - seg * WSZ4;
    const float* src;
    if (seg < 4)      src = pw_w + (size_t)seg * DDQ * DDQ;
    else if (seg == 4) src = wq;
    else if (seg == 5) src = wk;
    else if (seg == 6) src = wv;
    else if (seg == 7) src = wo;
    else               src = fw;
    float4 v = ((const float4*)src)[off4];
    __half2 h01 = __floats2half2_rn(v.x, v.y), h23 = __floats2half2_rn(v.z, v.w);
    uint2 o;
    o.x = *reinterpret_cast<uint32_t*>(&h01);
    o.y = *reinterpret_cast<uint32_t*>(&h23);
    *(uint2*)&g_wh[((size_t)seg * DDQ * DDQ) + off4 * 4] = o;
}

// ---------------- host orchestration -----------------------------------------
extern "C" void kernel_launch(void* const* d_in, const int* in_sizes, int n_in,
                              void* d_out, int out_size) {
    const float* x    = (const float*)d_in[0];
    const int*   mask = (const int*)  d_in[1];
    const float* dw_w = (const float*)d_in[2];
    const float* pw_w = (const float*)d_in[3];
    const float* pw_b = (const float*)d_in[4];
    const float* cg   = (const float*)d_in[5];
    const float* cb   = (const float*)d_in[6];
    const float* pg   = (const float*)d_in[7];
    const float* pb   = (const float*)d_in[8];
    const float* wq   = (const float*)d_in[9];
    const float* bq   = (const float*)d_in[10];
    const float* wk   = (const float*)d_in[11];
    const float* bk   = (const float*)d_in[12];
    const float* wv   = (const float*)d_in[13];
    const float* bv   = (const float*)d_in[14];
    const float* wo   = (const float*)d_in[15];
    const float* bo   = (const float*)d_in[16];
    const float* fg   = (const float*)d_in[17];
    const float* fb   = (const float*)d_in[18];
    const float* fw   = (const float*)d_in[19];
    const float* fbi  = (const float*)d_in[20];
    float* out = (float*)d_out;

    float* p_res;
    __half *p_xh, *p_yh, *p_wh, *p_qh, *p_qkv;
    cudaGetSymbolAddress((void**)&p_res, g_res);
    cudaGetSymbolAddress((void**)&p_xh,  g_xh);
    cudaGetSymbolAddress((void**)&p_yh,  g_yh);
    cudaGetSymbolAddress((void**)&p_wh,  g_wh);
    cudaGetSymbolAddress((void**)&p_qh,  g_qh);
    cudaGetSymbolAddress((void**)&p_qkv, g_qkv);

    const int WSZ = DDQ * DDQ;  // 262144
    dim3 dg(4, 48);             // N=512: N/128, M/128
    dim3 dg3(12, 48);           // N=1536 fused QKV

    // 0. weights -> fp16
    k_f2h_all<<<(9 * WSZ / 4 + 255) / 256, 256>>>(pw_w, wq, wk, wv, wo, fw);

    // 1. res = x + PE ; LN -> fp16 (conv input in g_qh)
    k_addpos_ln<<<MMQ, 128>>>(x, p_qh, pg, pb);

    // 2. conv stack: dwconv -> GEMM(Y fp16) -> addln (res += Y; LN)
    for (int l = 0; l < LLQ; l++) {
        k_dwconv_h<<<(MMQ / 4) * 128 / 256, 256>>>(p_qh, dw_w + l * DDQ * KKQ);
        k_gemm_h<1, 0><<<dg, 256>>>(p_xh, p_wh + (size_t)l * WSZ,
                                    pw_b + l * DDQ, nullptr, nullptr,
                                    nullptr, nullptr, p_yh);
        k_addln<<<MMQ, 128>>>(p_yh, (l < LLQ - 1) ? p_qh : p_xh,
                              cg + l * DDQ, cb + l * DDQ);
    }

    // 3. attention: fused QKV -> flash -> wo GEMM (Y fp16) -> addln (ff LN)
    k_gemm_h<0, 1><<<dg3, 256>>>(p_xh, p_wh + 4 * (size_t)WSZ,
                                 bq, bk, bv, nullptr, nullptr, p_qkv);
    k_flash<<<dim3(3, BHQ), 256>>>(mask);
    k_gemm_h<0, 0><<<dg, 256>>>(p_xh, p_wh + 7 * (size_t)WSZ,
                                bo, nullptr, nullptr, nullptr, nullptr, p_yh);
    k_addln<<<MMQ, 128>>>(p_yh, p_xh, fg, fb);

    // 4. feedforward final: out = relu(LN @ fw^T + fb) + res  (fp32 epilogue)
    k_gemm_h<1, 2><<<dg, 256>>>(p_xh, p_wh + 8 * (size_t)WSZ,
                                fbi, nullptr, nullptr, p_res, out, nullptr);
}